// round 1
// baseline (speedup 1.0000x reference)
#include <cuda_runtime.h>
#include <math.h>

#define B 4096
#define T 200
#define BT (B*T)

// ---------------- scratch (device globals: no allocs allowed) ----------------
__device__ float g_xg[(size_t)BT * 128];   // gate input projections (reused GRU1/GRU2)
__device__ float g_xc[(size_t)BT * 64];    // candidate input projections (reused)
__device__ float g_rnn1[(size_t)BT * 64];  // GRU1 states
__device__ float g_alpha[BT];              // attention weights
__device__ float g_final2[B * 64];         // GRU2 final state

__device__ __forceinline__ float sigmoidf_fast(float x) {
    return 1.0f / (1.0f + __expf(-x));
}

// ======================================================================
// Projection kernel: C[64 rows x 192 cols] = A[64x64] @ [Wg | Wc] + bias
// MODE 0: A rows gathered from item_emb via hist_i
// MODE 1: A rows = rnn1 rows scaled by alpha (att_in = rnn1 * alpha)
// 256 threads, micro-tile 8 rows x 6 cols per thread.
// ======================================================================
template<int MODE>
__global__ void proj_kernel(const float* __restrict__ src,       // emb table or rnn1
                            const int*   __restrict__ hist_i,    // MODE 0
                            const float* __restrict__ alpha,     // MODE 1
                            const float* __restrict__ Wg,        // [64,128]
                            const float* __restrict__ bg,        // [128]
                            const float* __restrict__ Wc,        // [64,64]
                            const float* __restrict__ bc,        // [64]
                            float* __restrict__ xg,              // [BT,128]
                            float* __restrict__ xc)              // [BT,64]
{
    extern __shared__ float sm[];
    float* As = sm;                 // [64][68] (A transposed: As[k][r])
    float* Ws = sm + 64 * 68;       // [64][196] (cols 0..127 = Wg, 128..191 = Wc)
    float* bs = Ws + 64 * 196;      // [192]

    const int tid = threadIdx.x;
    const int m0 = blockIdx.x * 64;

    // load weights
    for (int idx = tid; idx < 64 * 128; idx += 256) {
        int k = idx >> 7, c = idx & 127;
        Ws[k * 196 + c] = Wg[idx];
    }
    for (int idx = tid; idx < 64 * 64; idx += 256) {
        int k = idx >> 6, c = idx & 63;
        Ws[k * 196 + 128 + c] = Wc[idx];
    }
    if (tid < 128) bs[tid] = bg[tid];
    else if (tid < 192) bs[tid] = bc[tid - 128];

    // load A tile (gather), store transposed
    {
        int r = tid >> 2;
        int k0 = (tid & 3) << 4;
        const float* srow;
        float scale = 1.0f;
        if (MODE == 0) {
            int ix = hist_i[m0 + r];
            srow = src + (size_t)ix * 64;
        } else {
            srow = src + (size_t)(m0 + r) * 64;
            scale = alpha[m0 + r];
        }
#pragma unroll
        for (int i = 0; i < 4; i++) {
            float4 v = *(const float4*)(srow + k0 + i * 4);
            As[(k0 + i * 4 + 0) * 68 + r] = v.x * scale;
            As[(k0 + i * 4 + 1) * 68 + r] = v.y * scale;
            As[(k0 + i * 4 + 2) * 68 + r] = v.z * scale;
            As[(k0 + i * 4 + 3) * 68 + r] = v.w * scale;
        }
    }
    __syncthreads();

    const int tx = tid & 31;   // column group: cols tx*6 .. tx*6+5
    const int ty = tid >> 5;   // row group:    rows ty*8 .. ty*8+7

    float acc[8][6];
#pragma unroll
    for (int i = 0; i < 8; i++)
#pragma unroll
        for (int j = 0; j < 6; j++) acc[i][j] = 0.0f;

#pragma unroll 16
    for (int k = 0; k < 64; k++) {
        float4 a0 = *(const float4*)(As + k * 68 + ty * 8);
        float4 a1 = *(const float4*)(As + k * 68 + ty * 8 + 4);
        float av[8] = {a0.x, a0.y, a0.z, a0.w, a1.x, a1.y, a1.z, a1.w};
        const float* wrow = Ws + k * 196 + tx * 6;
        float2 w0 = *(const float2*)(wrow);
        float2 w1 = *(const float2*)(wrow + 2);
        float2 w2 = *(const float2*)(wrow + 4);
        float bv[6] = {w0.x, w0.y, w1.x, w1.y, w2.x, w2.y};
#pragma unroll
        for (int i = 0; i < 8; i++)
#pragma unroll
            for (int j = 0; j < 6; j++)
                acc[i][j] = fmaf(av[i], bv[j], acc[i][j]);
    }

#pragma unroll
    for (int i = 0; i < 8; i++) {
        int m = m0 + ty * 8 + i;
#pragma unroll
        for (int j = 0; j < 6; j++) {
            int col = tx * 6 + j;
            float v = acc[i][j] + bs[col];
            if (col < 128) xg[(size_t)m * 128 + col] = v;
            else           xc[(size_t)m * 64 + (col - 128)] = v;
        }
    }
}

// ======================================================================
// GRU recurrence. 256 threads = 2 batch rows x 128 threads.
// Per step: g = sigmoid(xg + h@Ug); r=g[:64], z=g[64:];
//           c = tanh(xc + (r*h)@Uc); hn = z*h+(1-z)*c; h = m*hn+(1-m)*h
// ======================================================================
template<bool STORE_ALL>
__global__ void gru_kernel(const float* __restrict__ xg,
                           const float* __restrict__ xc,
                           const float* __restrict__ mask,
                           const float* __restrict__ Ug,  // [64,128]
                           const float* __restrict__ Uc,  // [64,64]
                           float* __restrict__ out)       // [B,T,64] or [B,64]
{
    extern __shared__ float sm[];
    float* Ugs = sm;                 // [64][128]
    float* Ucs = Ugs + 64 * 128;     // [64][64]
    float* rowbuf = Ucs + 64 * 64;   // 2 * (hs64 + zs64 + rhs64)

    const int tid = threadIdx.x;
    const int sub = tid >> 7;
    const int j = tid & 127;
    const int row = blockIdx.x * 2 + sub;

    float* hs  = rowbuf + sub * 192;
    float* zs  = hs + 64;
    float* rhs = zs + 64;

    for (int idx = tid; idx < 64 * 128; idx += 256) Ugs[idx] = Ug[idx];
    for (int idx = tid; idx < 64 * 64; idx += 256)  Ucs[idx] = Uc[idx];
    if (j < 64) hs[j] = 0.0f;
    __syncthreads();

    const float* xg_row = xg + (size_t)row * T * 128;
    const float* xc_row = xc + (size_t)row * T * 64;
    const float* m_row  = mask + (size_t)row * T;
    float* out_row = STORE_ALL ? (out + (size_t)row * T * 64)
                               : (out + (size_t)row * 64);

    for (int t = 0; t < T; t++) {
        // gate dot: all 128 threads, one gate column each
        float a0 = xg_row[t * 128 + j];
        float a1 = 0.0f;
#pragma unroll 16
        for (int k = 0; k < 64; k += 2) {
            a0 = fmaf(hs[k],     Ugs[k * 128 + j],       a0);
            a1 = fmaf(hs[k + 1], Ugs[(k + 1) * 128 + j], a1);
        }
        float g = sigmoidf_fast(a0 + a1);
        if (j < 64) rhs[j] = g * hs[j];     // r_j * h_j
        else        zs[j - 64] = g;
        __syncthreads();

        float hnew = 0.0f;
        if (j < 64) {
            float c0 = xc_row[t * 64 + j];
            float c1 = 0.0f;
#pragma unroll 16
            for (int k = 0; k < 64; k += 2) {
                c0 = fmaf(rhs[k],     Ucs[k * 64 + j],       c0);
                c1 = fmaf(rhs[k + 1], Ucs[(k + 1) * 64 + j], c1);
            }
            float c = tanhf(c0 + c1);
            float z = zs[j];
            float h = hs[j];
            float hn = z * h + (1.0f - z) * c;
            float m = m_row[t];
            hnew = m * hn + (1.0f - m) * h;
            if (STORE_ALL) out_row[t * 64 + j] = hnew;
        }
        __syncthreads();
        if (j < 64) hs[j] = hnew;
        __syncthreads();
    }

    if (!STORE_ALL && j < 64 && sub * 0 == 0) out_row[j] = hs[j];
}

// ======================================================================
// DIN attention + masked softmax. One block (256 thr) per batch row.
// din@Wa1 folded: base[c] = ba1 + q@(W0+W2); Weff[k][c] = (W1-W2)[k][c] + q_k*W3[k][c]
// ======================================================================
__global__ void attn_kernel(const int*   __restrict__ item_i,
                            const float* __restrict__ item_emb,
                            const float* __restrict__ rnn1,
                            const float* __restrict__ mask,
                            const float* __restrict__ Wa1, const float* __restrict__ ba1,
                            const float* __restrict__ Wa2, const float* __restrict__ ba2,
                            const float* __restrict__ Wa3, const float* __restrict__ ba3,
                            float* __restrict__ alpha)
{
    extern __shared__ float sm[];
    float* Weff = sm;                  // [64][80]
    float* base = Weff + 64 * 80;      // [80]
    float* Wa2s = base + 80;           // [80][40]
    float* ba2s = Wa2s + 80 * 40;      // [40]
    float* Wa3s = ba2s + 40;           // [40]
    float* qs   = Wa3s + 40;           // [64]
    float* Ks   = qs + 64;             // [8][64]
    float* d1s  = Ks + 8 * 64;         // [8][80]
    float* d2s  = d1s + 8 * 80;        // [8][40]
    float* sc   = d2s + 8 * 40;        // [200]
    float* red  = sc + 200;            // [32]

    const int b = blockIdx.x;
    const int tid = threadIdx.x;

    if (tid < 64) qs[tid] = item_emb[(size_t)item_i[b] * 64 + tid];
    __syncthreads();

    if (tid < 80) {
        int c = tid;
        float acc = ba1[c];
#pragma unroll 8
        for (int k = 0; k < 64; k++)
            acc = fmaf(qs[k], Wa1[k * 80 + c] + Wa1[(128 + k) * 80 + c], acc);
        base[c] = acc;
    }
    for (int idx = tid; idx < 64 * 80; idx += 256) {
        int k = idx / 80, c = idx - k * 80;
        Weff[idx] = Wa1[(64 + k) * 80 + c] - Wa1[(128 + k) * 80 + c]
                  + qs[k] * Wa1[(192 + k) * 80 + c];
    }
    for (int idx = tid; idx < 80 * 40; idx += 256) Wa2s[idx] = Wa2[idx];
    if (tid < 40) { ba2s[tid] = ba2[tid]; Wa3s[tid] = Wa3[tid]; }
    __syncthreads();

    const float ba3v = ba3[0];

    for (int tt0 = 0; tt0 < T; tt0 += 8) {
        for (int idx = tid; idx < 512; idx += 256) {
            int t = idx >> 6, k = idx & 63;
            Ks[idx] = rnn1[((size_t)b * T + tt0 + t) * 64 + k];
        }
        __syncthreads();

        // layer 1: 8*80 outputs
        for (int o = tid; o < 640; o += 256) {
            int t = o / 80, c = o - t * 80;
            float a0 = base[c], a1 = 0.0f;
#pragma unroll 16
            for (int k = 0; k < 64; k += 2) {
                a0 = fmaf(Ks[t * 64 + k],     Weff[k * 80 + c],       a0);
                a1 = fmaf(Ks[t * 64 + k + 1], Weff[(k + 1) * 80 + c], a1);
            }
            d1s[o] = sigmoidf_fast(a0 + a1);
        }
        __syncthreads();

        // layer 2: 8*40 outputs
        if (tid < 320) {
            int t = tid / 40, c = tid - t * 40;
            float a0 = ba2s[c], a1 = 0.0f;
#pragma unroll 16
            for (int k = 0; k < 80; k += 2) {
                a0 = fmaf(d1s[t * 80 + k],     Wa2s[k * 40 + c],       a0);
                a1 = fmaf(d1s[t * 80 + k + 1], Wa2s[(k + 1) * 40 + c], a1);
            }
            d2s[tid] = sigmoidf_fast(a0 + a1);
        }
        __syncthreads();

        // layer 3: 8 scores + mask
        if (tid < 8) {
            float acc = ba3v;
#pragma unroll
            for (int k = 0; k < 40; k++)
                acc = fmaf(d2s[tid * 40 + k], Wa3s[k], acc);
            float m = mask[(size_t)b * T + tt0 + tid];
            sc[tt0 + tid] = (m > 0.0f) ? acc : -1e9f;
        }
        __syncthreads();
    }

    // masked softmax over 200
    float v = (tid < T) ? sc[tid] : -3.0e38f;
#pragma unroll
    for (int o = 16; o > 0; o >>= 1) v = fmaxf(v, __shfl_xor_sync(0xffffffffu, v, o));
    if ((tid & 31) == 0) red[tid >> 5] = v;
    __syncthreads();
    if (tid == 0) {
        float mx = red[0];
#pragma unroll
        for (int w = 1; w < 8; w++) mx = fmaxf(mx, red[w]);
        red[8] = mx;
    }
    __syncthreads();
    float mx = red[8];

    float e = (tid < T) ? __expf(sc[tid] - mx) : 0.0f;
    float s = e;
#pragma unroll
    for (int o = 16; o > 0; o >>= 1) s += __shfl_xor_sync(0xffffffffu, s, o);
    __syncthreads();
    if ((tid & 31) == 0) red[tid >> 5] = s;
    __syncthreads();
    if (tid == 0) {
        float sum = 0.0f;
#pragma unroll
        for (int w = 0; w < 8; w++) sum += red[w];
        red[9] = 1.0f / sum;
    }
    __syncthreads();
    if (tid < T) alpha[(size_t)b * T + tid] = e * red[9];
}

// ======================================================================
// FCN head + hist_sum. One block (128 thr) per batch row.
// x = [user, item, hist_sum, item*hist_sum, final2] (320)
// ======================================================================
__global__ void fcn_kernel(const int* __restrict__ u, const int* __restrict__ ii,
                           const int* __restrict__ hist_i,
                           const float* __restrict__ item_emb,
                           const float* __restrict__ user_emb,
                           const float* __restrict__ final2,
                           const float* __restrict__ W1, const float* __restrict__ b1,
                           const float* __restrict__ p1,
                           const float* __restrict__ W2, const float* __restrict__ b2,
                           const float* __restrict__ p2,
                           const float* __restrict__ W3, const float* __restrict__ b3,
                           float* __restrict__ out)
{
    __shared__ float xs[320];
    __shared__ float h1s[128];
    __shared__ float h2s[40];

    const int b = blockIdx.x;
    const int tid = threadIdx.x;

    if (tid < 64) {
        // hist_sum (unmasked, per reference)
        const int* hi = hist_i + (size_t)b * T;
        float s0 = 0.f, s1 = 0.f, s2 = 0.f, s3 = 0.f;
        for (int t = 0; t < T; t += 4) {
            s0 += item_emb[(size_t)hi[t]     * 64 + tid];
            s1 += item_emb[(size_t)hi[t + 1] * 64 + tid];
            s2 += item_emb[(size_t)hi[t + 2] * 64 + tid];
            s3 += item_emb[(size_t)hi[t + 3] * 64 + tid];
        }
        xs[128 + tid] = (s0 + s1) + (s2 + s3);
    } else {
        int j = tid - 64;
        xs[j]       = user_emb[(size_t)u[b]  * 64 + j];
        xs[64 + j]  = item_emb[(size_t)ii[b] * 64 + j];
        xs[256 + j] = final2[(size_t)b * 64 + j];
    }
    __syncthreads();
    if (tid < 64) xs[192 + tid] = xs[64 + tid] * xs[128 + tid];
    __syncthreads();

    {
        float a0 = b1[tid], a1 = 0.0f;
#pragma unroll 8
        for (int k = 0; k < 320; k += 2) {
            a0 = fmaf(xs[k],     W1[k * 128 + tid],       a0);
            a1 = fmaf(xs[k + 1], W1[(k + 1) * 128 + tid], a1);
        }
        float h = a0 + a1;
        h1s[tid] = (h >= 0.0f) ? h : p1[tid] * h;
    }
    __syncthreads();

    if (tid < 40) {
        float a0 = b2[tid], a1 = 0.0f;
#pragma unroll 16
        for (int k = 0; k < 128; k += 2) {
            a0 = fmaf(h1s[k],     W2[k * 40 + tid],       a0);
            a1 = fmaf(h1s[k + 1], W2[(k + 1) * 40 + tid], a1);
        }
        float h = a0 + a1;
        h2s[tid] = (h >= 0.0f) ? h : p2[tid] * h;
    }
    __syncthreads();

    if (tid == 0) {
        float acc = b3[0];
#pragma unroll
        for (int k = 0; k < 40; k++) acc = fmaf(h2s[k], W3[k], acc);
        out[b] = acc;
    }
}

// ======================================================================
extern "C" void kernel_launch(void* const* d_in, const int* in_sizes, int n_in,
                              void* d_out, int out_size)
{
    const int*   u        = (const int*)d_in[0];
    const int*   ii       = (const int*)d_in[1];
    const int*   hist_i   = (const int*)d_in[2];
    const float* mask     = (const float*)d_in[3];
    const float* item_emb = (const float*)d_in[4];
    const float* user_emb = (const float*)d_in[5];
    const float* g1_Wg = (const float*)d_in[6];
    const float* g1_Ug = (const float*)d_in[7];
    const float* g1_bg = (const float*)d_in[8];
    const float* g1_Wc = (const float*)d_in[9];
    const float* g1_Uc = (const float*)d_in[10];
    const float* g1_bc = (const float*)d_in[11];
    const float* Wa1 = (const float*)d_in[12];
    const float* ba1 = (const float*)d_in[13];
    const float* Wa2 = (const float*)d_in[14];
    const float* ba2 = (const float*)d_in[15];
    const float* Wa3 = (const float*)d_in[16];
    const float* ba3 = (const float*)d_in[17];
    const float* g2_Wg = (const float*)d_in[18];
    const float* g2_Ug = (const float*)d_in[19];
    const float* g2_bg = (const float*)d_in[20];
    const float* g2_Wc = (const float*)d_in[21];
    const float* g2_Uc = (const float*)d_in[22];
    const float* g2_bc = (const float*)d_in[23];
    const float* W1 = (const float*)d_in[24];
    const float* b1 = (const float*)d_in[25];
    const float* p1 = (const float*)d_in[26];
    const float* W2 = (const float*)d_in[27];
    const float* b2 = (const float*)d_in[28];
    const float* p2 = (const float*)d_in[29];
    const float* W3 = (const float*)d_in[30];
    const float* b3 = (const float*)d_in[31];
    float* out = (float*)d_out;

    float *xg, *xc, *rnn1, *alpha, *final2;
    cudaGetSymbolAddress((void**)&xg,     g_xg);
    cudaGetSymbolAddress((void**)&xc,     g_xc);
    cudaGetSymbolAddress((void**)&rnn1,   g_rnn1);
    cudaGetSymbolAddress((void**)&alpha,  g_alpha);
    cudaGetSymbolAddress((void**)&final2, g_final2);

    const int PROJ_SMEM = (64 * 68 + 64 * 196 + 192) * 4;   // 68352
    const int GRU_SMEM  = (64 * 128 + 64 * 64 + 2 * 192) * 4; // 50688
    const int ATTN_SMEM = (64*80 + 80 + 80*40 + 40 + 40 + 64 + 8*64 + 8*80 + 8*40 + 200 + 32) * 4; // 40992

    cudaFuncSetAttribute(proj_kernel<0>, cudaFuncAttributeMaxDynamicSharedMemorySize, PROJ_SMEM);
    cudaFuncSetAttribute(proj_kernel<1>, cudaFuncAttributeMaxDynamicSharedMemorySize, PROJ_SMEM);
    cudaFuncSetAttribute(gru_kernel<true>,  cudaFuncAttributeMaxDynamicSharedMemorySize, GRU_SMEM);
    cudaFuncSetAttribute(gru_kernel<false>, cudaFuncAttributeMaxDynamicSharedMemorySize, GRU_SMEM);
    cudaFuncSetAttribute(attn_kernel, cudaFuncAttributeMaxDynamicSharedMemorySize, ATTN_SMEM);

    // 1) input projections for GRU1 (gathered embeddings)
    proj_kernel<0><<<BT / 64, 256, PROJ_SMEM>>>(item_emb, hist_i, nullptr,
                                                g1_Wg, g1_bg, g1_Wc, g1_bc, xg, xc);
    // 2) GRU1 recurrence -> rnn1
    gru_kernel<true><<<B / 2, 256, GRU_SMEM>>>(xg, xc, mask, g1_Ug, g1_Uc, rnn1);
    // 3) DIN attention -> alpha
    attn_kernel<<<B, 256, ATTN_SMEM>>>(ii, item_emb, rnn1, mask,
                                       Wa1, ba1, Wa2, ba2, Wa3, ba3, alpha);
    // 4) projections for GRU2 (rnn1 * alpha)
    proj_kernel<1><<<BT / 64, 256, PROJ_SMEM>>>(rnn1, nullptr, alpha,
                                                g2_Wg, g2_bg, g2_Wc, g2_bc, xg, xc);
    // 5) GRU2 recurrence -> final2 only
    gru_kernel<false><<<B / 2, 256, GRU_SMEM>>>(xg, xc, mask, g2_Ug, g2_Uc, final2);
    // 6) FCN head (computes hist_sum internally) -> logits
    fcn_kernel<<<B, 128>>>(u, ii, hist_i, item_emb, user_emb, final2,
                           W1, b1, p1, W2, b2, p2, W3, b3, out);
}

// round 2
// speedup vs baseline: 1.0013x; 1.0013x over previous
#include <cuda_runtime.h>
#include <math.h>

#define B 4096
#define T 200
#define BT (B*T)

// ---------------- scratch (device globals: no allocs allowed) ----------------
__device__ float g_xg[(size_t)BT * 128];   // gate input projections (reused GRU1/GRU2)
__device__ float g_xc[(size_t)BT * 64];    // candidate input projections (reused)
__device__ float g_rnn1[(size_t)BT * 64];  // GRU1 states
__device__ float g_alpha[BT];              // attention weights
__device__ float g_final2[B * 64];         // GRU2 final state

__device__ __forceinline__ float sigmoidf_fast(float x) {
    return 1.0f / (1.0f + __expf(-x));
}

// ======================================================================
// Projection kernel: C[64 rows x 192 cols] = A[64x64] @ [Wg | Wc] + bias
// MODE 0: A rows gathered from item_emb via hist_i
// MODE 1: A rows = rnn1 rows scaled by alpha (att_in = rnn1 * alpha)
// 256 threads, micro-tile 8 rows x 6 cols per thread.
// ======================================================================
template<int MODE>
__global__ void proj_kernel(const float* __restrict__ src,       // emb table or rnn1
                            const int*   __restrict__ hist_i,    // MODE 0
                            const float* __restrict__ alpha,     // MODE 1
                            const float* __restrict__ Wg,        // [64,128]
                            const float* __restrict__ bg,        // [128]
                            const float* __restrict__ Wc,        // [64,64]
                            const float* __restrict__ bc,        // [64]
                            float* __restrict__ xg,              // [BT,128]
                            float* __restrict__ xc)              // [BT,64]
{
    extern __shared__ float sm[];
    float* As = sm;                 // [64][68] (A transposed: As[k][r])
    float* Ws = sm + 64 * 68;       // [64][196] (cols 0..127 = Wg, 128..191 = Wc)
    float* bs = Ws + 64 * 196;      // [192]

    const int tid = threadIdx.x;
    const int m0 = blockIdx.x * 64;

    // load weights
    for (int idx = tid; idx < 64 * 128; idx += 256) {
        int k = idx >> 7, c = idx & 127;
        Ws[k * 196 + c] = Wg[idx];
    }
    for (int idx = tid; idx < 64 * 64; idx += 256) {
        int k = idx >> 6, c = idx & 63;
        Ws[k * 196 + 128 + c] = Wc[idx];
    }
    if (tid < 128) bs[tid] = bg[tid];
    else if (tid < 192) bs[tid] = bc[tid - 128];

    // load A tile (gather), store transposed
    {
        int r = tid >> 2;
        int k0 = (tid & 3) << 4;
        const float* srow;
        float scale = 1.0f;
        if (MODE == 0) {
            int ix = hist_i[m0 + r];
            srow = src + (size_t)ix * 64;
        } else {
            srow = src + (size_t)(m0 + r) * 64;
            scale = alpha[m0 + r];
        }
#pragma unroll
        for (int i = 0; i < 4; i++) {
            float4 v = *(const float4*)(srow + k0 + i * 4);
            As[(k0 + i * 4 + 0) * 68 + r] = v.x * scale;
            As[(k0 + i * 4 + 1) * 68 + r] = v.y * scale;
            As[(k0 + i * 4 + 2) * 68 + r] = v.z * scale;
            As[(k0 + i * 4 + 3) * 68 + r] = v.w * scale;
        }
    }
    __syncthreads();

    const int tx = tid & 31;   // column group: cols tx*6 .. tx*6+5
    const int ty = tid >> 5;   // row group:    rows ty*8 .. ty*8+7

    float acc[8][6];
#pragma unroll
    for (int i = 0; i < 8; i++)
#pragma unroll
        for (int j = 0; j < 6; j++) acc[i][j] = 0.0f;

#pragma unroll 16
    for (int k = 0; k < 64; k++) {
        float4 a0 = *(const float4*)(As + k * 68 + ty * 8);
        float4 a1 = *(const float4*)(As + k * 68 + ty * 8 + 4);
        float av[8] = {a0.x, a0.y, a0.z, a0.w, a1.x, a1.y, a1.z, a1.w};
        const float* wrow = Ws + k * 196 + tx * 6;
        float2 w0 = *(const float2*)(wrow);
        float2 w1 = *(const float2*)(wrow + 2);
        float2 w2 = *(const float2*)(wrow + 4);
        float bv[6] = {w0.x, w0.y, w1.x, w1.y, w2.x, w2.y};
#pragma unroll
        for (int i = 0; i < 8; i++)
#pragma unroll
            for (int j = 0; j < 6; j++)
                acc[i][j] = fmaf(av[i], bv[j], acc[i][j]);
    }

#pragma unroll
    for (int i = 0; i < 8; i++) {
        int m = m0 + ty * 8 + i;
#pragma unroll
        for (int j = 0; j < 6; j++) {
            int col = tx * 6 + j;
            float v = acc[i][j] + bs[col];
            if (col < 128) xg[(size_t)m * 128 + col] = v;
            else           xc[(size_t)m * 64 + (col - 128)] = v;
        }
    }
}

// ======================================================================
// GRU recurrence. 256 threads = 2 batch rows x 128 threads.
// Per step: g = sigmoid(xg + h@Ug); r=g[:64], z=g[64:];
//           c = tanh(xc + (r*h)@Uc); hn = z*h+(1-z)*c; h = m*hn+(1-m)*h
// ======================================================================
template<bool STORE_ALL>
__global__ void gru_kernel(const float* __restrict__ xg,
                           const float* __restrict__ xc,
                           const float* __restrict__ mask,
                           const float* __restrict__ Ug,  // [64,128]
                           const float* __restrict__ Uc,  // [64,64]
                           float* __restrict__ out)       // [B,T,64] or [B,64]
{
    extern __shared__ float sm[];
    float* Ugs = sm;                 // [64][128]
    float* Ucs = Ugs + 64 * 128;     // [64][64]
    float* rowbuf = Ucs + 64 * 64;   // 2 * (hs64 + zs64 + rhs64)

    const int tid = threadIdx.x;
    const int sub = tid >> 7;
    const int j = tid & 127;
    const int row = blockIdx.x * 2 + sub;

    float* hs  = rowbuf + sub * 192;
    float* zs  = hs + 64;
    float* rhs = zs + 64;

    for (int idx = tid; idx < 64 * 128; idx += 256) Ugs[idx] = Ug[idx];
    for (int idx = tid; idx < 64 * 64; idx += 256)  Ucs[idx] = Uc[idx];
    if (j < 64) hs[j] = 0.0f;
    __syncthreads();

    const float* xg_row = xg + (size_t)row * T * 128;
    const float* xc_row = xc + (size_t)row * T * 64;
    const float* m_row  = mask + (size_t)row * T;
    float* out_row = STORE_ALL ? (out + (size_t)row * T * 64)
                               : (out + (size_t)row * 64);

    for (int t = 0; t < T; t++) {
        // gate dot: all 128 threads, one gate column each
        float a0 = xg_row[t * 128 + j];
        float a1 = 0.0f;
#pragma unroll 16
        for (int k = 0; k < 64; k += 2) {
            a0 = fmaf(hs[k],     Ugs[k * 128 + j],       a0);
            a1 = fmaf(hs[k + 1], Ugs[(k + 1) * 128 + j], a1);
        }
        float g = sigmoidf_fast(a0 + a1);
        if (j < 64) rhs[j] = g * hs[j];     // r_j * h_j
        else        zs[j - 64] = g;
        __syncthreads();

        float hnew = 0.0f;
        if (j < 64) {
            float c0 = xc_row[t * 64 + j];
            float c1 = 0.0f;
#pragma unroll 16
            for (int k = 0; k < 64; k += 2) {
                c0 = fmaf(rhs[k],     Ucs[k * 64 + j],       c0);
                c1 = fmaf(rhs[k + 1], Ucs[(k + 1) * 64 + j], c1);
            }
            float c = tanhf(c0 + c1);
            float z = zs[j];
            float h = hs[j];
            float hn = z * h + (1.0f - z) * c;
            float m = m_row[t];
            hnew = m * hn + (1.0f - m) * h;
            if (STORE_ALL) out_row[t * 64 + j] = hnew;
        }
        __syncthreads();
        if (j < 64) hs[j] = hnew;
        __syncthreads();
    }

    if (!STORE_ALL && j < 64 && sub * 0 == 0) out_row[j] = hs[j];
}

// ======================================================================
// DIN attention + masked softmax. One block (256 thr) per batch row.
// din@Wa1 folded: base[c] = ba1 + q@(W0+W2); Weff[k][c] = (W1-W2)[k][c] + q_k*W3[k][c]
// ======================================================================
__global__ void attn_kernel(const int*   __restrict__ item_i,
                            const float* __restrict__ item_emb,
                            const float* __restrict__ rnn1,
                            const float* __restrict__ mask,
                            const float* __restrict__ Wa1, const float* __restrict__ ba1,
                            const float* __restrict__ Wa2, const float* __restrict__ ba2,
                            const float* __restrict__ Wa3, const float* __restrict__ ba3,
                            float* __restrict__ alpha)
{
    extern __shared__ float sm[];
    float* Weff = sm;                  // [64][80]
    float* base = Weff + 64 * 80;      // [80]
    float* Wa2s = base + 80;           // [80][40]
    float* ba2s = Wa2s + 80 * 40;      // [40]
    float* Wa3s = ba2s + 40;           // [40]
    float* qs   = Wa3s + 40;           // [64]
    float* Ks   = qs + 64;             // [8][64]
    float* d1s  = Ks + 8 * 64;         // [8][80]
    float* d2s  = d1s + 8 * 80;        // [8][40]
    float* sc   = d2s + 8 * 40;        // [200]
    float* red  = sc + 200;            // [32]

    const int b = blockIdx.x;
    const int tid = threadIdx.x;

    if (tid < 64) qs[tid] = item_emb[(size_t)item_i[b] * 64 + tid];
    __syncthreads();

    if (tid < 80) {
        int c = tid;
        float acc = ba1[c];
#pragma unroll 8
        for (int k = 0; k < 64; k++)
            acc = fmaf(qs[k], Wa1[k * 80 + c] + Wa1[(128 + k) * 80 + c], acc);
        base[c] = acc;
    }
    for (int idx = tid; idx < 64 * 80; idx += 256) {
        int k = idx / 80, c = idx - k * 80;
        Weff[idx] = Wa1[(64 + k) * 80 + c] - Wa1[(128 + k) * 80 + c]
                  + qs[k] * Wa1[(192 + k) * 80 + c];
    }
    for (int idx = tid; idx < 80 * 40; idx += 256) Wa2s[idx] = Wa2[idx];
    if (tid < 40) { ba2s[tid] = ba2[tid]; Wa3s[tid] = Wa3[tid]; }
    __syncthreads();

    const float ba3v = ba3[0];

    for (int tt0 = 0; tt0 < T; tt0 += 8) {
        for (int idx = tid; idx < 512; idx += 256) {
            int t = idx >> 6, k = idx & 63;
            Ks[idx] = rnn1[((size_t)b * T + tt0 + t) * 64 + k];
        }
        __syncthreads();

        // layer 1: 8*80 outputs
        for (int o = tid; o < 640; o += 256) {
            int t = o / 80, c = o - t * 80;
            float a0 = base[c], a1 = 0.0f;
#pragma unroll 16
            for (int k = 0; k < 64; k += 2) {
                a0 = fmaf(Ks[t * 64 + k],     Weff[k * 80 + c],       a0);
                a1 = fmaf(Ks[t * 64 + k + 1], Weff[(k + 1) * 80 + c], a1);
            }
            d1s[o] = sigmoidf_fast(a0 + a1);
        }
        __syncthreads();

        // layer 2: 8*40 outputs
        if (tid < 320) {
            int t = tid / 40, c = tid - t * 40;
            float a0 = ba2s[c], a1 = 0.0f;
#pragma unroll 16
            for (int k = 0; k < 80; k += 2) {
                a0 = fmaf(d1s[t * 80 + k],     Wa2s[k * 40 + c],       a0);
                a1 = fmaf(d1s[t * 80 + k + 1], Wa2s[(k + 1) * 40 + c], a1);
            }
            d2s[tid] = sigmoidf_fast(a0 + a1);
        }
        __syncthreads();

        // layer 3: 8 scores + mask
        if (tid < 8) {
            float acc = ba3v;
#pragma unroll
            for (int k = 0; k < 40; k++)
                acc = fmaf(d2s[tid * 40 + k], Wa3s[k], acc);
            float m = mask[(size_t)b * T + tt0 + tid];
            sc[tt0 + tid] = (m > 0.0f) ? acc : -1e9f;
        }
        __syncthreads();
    }

    // masked softmax over 200
    float v = (tid < T) ? sc[tid] : -3.0e38f;
#pragma unroll
    for (int o = 16; o > 0; o >>= 1) v = fmaxf(v, __shfl_xor_sync(0xffffffffu, v, o));
    if ((tid & 31) == 0) red[tid >> 5] = v;
    __syncthreads();
    if (tid == 0) {
        float mx = red[0];
#pragma unroll
        for (int w = 1; w < 8; w++) mx = fmaxf(mx, red[w]);
        red[8] = mx;
    }
    __syncthreads();
    float mx = red[8];

    float e = (tid < T) ? __expf(sc[tid] - mx) : 0.0f;
    float s = e;
#pragma unroll
    for (int o = 16; o > 0; o >>= 1) s += __shfl_xor_sync(0xffffffffu, s, o);
    __syncthreads();
    if ((tid & 31) == 0) red[tid >> 5] = s;
    __syncthreads();
    if (tid == 0) {
        float sum = 0.0f;
#pragma unroll
        for (int w = 0; w < 8; w++) sum += red[w];
        red[9] = 1.0f / sum;
    }
    __syncthreads();
    if (tid < T) alpha[(size_t)b * T + tid] = e * red[9];
}

// ======================================================================
// FCN head + hist_sum. One block (128 thr) per batch row.
// x = [user, item, hist_sum, item*hist_sum, final2] (320)
// ======================================================================
__global__ void fcn_kernel(const int* __restrict__ u, const int* __restrict__ ii,
                           const int* __restrict__ hist_i,
                           const float* __restrict__ item_emb,
                           const float* __restrict__ user_emb,
                           const float* __restrict__ final2,
                           const float* __restrict__ W1, const float* __restrict__ b1,
                           const float* __restrict__ p1,
                           const float* __restrict__ W2, const float* __restrict__ b2,
                           const float* __restrict__ p2,
                           const float* __restrict__ W3, const float* __restrict__ b3,
                           float* __restrict__ out)
{
    __shared__ float xs[320];
    __shared__ float h1s[128];
    __shared__ float h2s[40];

    const int b = blockIdx.x;
    const int tid = threadIdx.x;

    if (tid < 64) {
        // hist_sum (unmasked, per reference)
        const int* hi = hist_i + (size_t)b * T;
        float s0 = 0.f, s1 = 0.f, s2 = 0.f, s3 = 0.f;
        for (int t = 0; t < T; t += 4) {
            s0 += item_emb[(size_t)hi[t]     * 64 + tid];
            s1 += item_emb[(size_t)hi[t + 1] * 64 + tid];
            s2 += item_emb[(size_t)hi[t + 2] * 64 + tid];
            s3 += item_emb[(size_t)hi[t + 3] * 64 + tid];
        }
        xs[128 + tid] = (s0 + s1) + (s2 + s3);
    } else {
        int j = tid - 64;
        xs[j]       = user_emb[(size_t)u[b]  * 64 + j];
        xs[64 + j]  = item_emb[(size_t)ii[b] * 64 + j];
        xs[256 + j] = final2[(size_t)b * 64 + j];
    }
    __syncthreads();
    if (tid < 64) xs[192 + tid] = xs[64 + tid] * xs[128 + tid];
    __syncthreads();

    {
        float a0 = b1[tid], a1 = 0.0f;
#pragma unroll 8
        for (int k = 0; k < 320; k += 2) {
            a0 = fmaf(xs[k],     W1[k * 128 + tid],       a0);
            a1 = fmaf(xs[k + 1], W1[(k + 1) * 128 + tid], a1);
        }
        float h = a0 + a1;
        h1s[tid] = (h >= 0.0f) ? h : p1[tid] * h;
    }
    __syncthreads();

    if (tid < 40) {
        float a0 = b2[tid], a1 = 0.0f;
#pragma unroll 16
        for (int k = 0; k < 128; k += 2) {
            a0 = fmaf(h1s[k],     W2[k * 40 + tid],       a0);
            a1 = fmaf(h1s[k + 1], W2[(k + 1) * 40 + tid], a1);
        }
        float h = a0 + a1;
        h2s[tid] = (h >= 0.0f) ? h : p2[tid] * h;
    }
    __syncthreads();

    if (tid == 0) {
        float acc = b3[0];
#pragma unroll
        for (int k = 0; k < 40; k++) acc = fmaf(h2s[k], W3[k], acc);
        out[b] = acc;
    }
}

// ======================================================================
extern "C" void kernel_launch(void* const* d_in, const int* in_sizes, int n_in,
                              void* d_out, int out_size)
{
    const int*   u        = (const int*)d_in[0];
    const int*   ii       = (const int*)d_in[1];
    const int*   hist_i   = (const int*)d_in[2];
    const float* mask     = (const float*)d_in[3];
    const float* item_emb = (const float*)d_in[4];
    const float* user_emb = (const float*)d_in[5];
    const float* g1_Wg = (const float*)d_in[6];
    const float* g1_Ug = (const float*)d_in[7];
    const float* g1_bg = (const float*)d_in[8];
    const float* g1_Wc = (const float*)d_in[9];
    const float* g1_Uc = (const float*)d_in[10];
    const float* g1_bc = (const float*)d_in[11];
    const float* Wa1 = (const float*)d_in[12];
    const float* ba1 = (const float*)d_in[13];
    const float* Wa2 = (const float*)d_in[14];
    const float* ba2 = (const float*)d_in[15];
    const float* Wa3 = (const float*)d_in[16];
    const float* ba3 = (const float*)d_in[17];
    const float* g2_Wg = (const float*)d_in[18];
    const float* g2_Ug = (const float*)d_in[19];
    const float* g2_bg = (const float*)d_in[20];
    const float* g2_Wc = (const float*)d_in[21];
    const float* g2_Uc = (const float*)d_in[22];
    const float* g2_bc = (const float*)d_in[23];
    const float* W1 = (const float*)d_in[24];
    const float* b1 = (const float*)d_in[25];
    const float* p1 = (const float*)d_in[26];
    const float* W2 = (const float*)d_in[27];
    const float* b2 = (const float*)d_in[28];
    const float* p2 = (const float*)d_in[29];
    const float* W3 = (const float*)d_in[30];
    const float* b3 = (const float*)d_in[31];
    float* out = (float*)d_out;

    float *xg, *xc, *rnn1, *alpha, *final2;
    cudaGetSymbolAddress((void**)&xg,     g_xg);
    cudaGetSymbolAddress((void**)&xc,     g_xc);
    cudaGetSymbolAddress((void**)&rnn1,   g_rnn1);
    cudaGetSymbolAddress((void**)&alpha,  g_alpha);
    cudaGetSymbolAddress((void**)&final2, g_final2);

    const int PROJ_SMEM = (64 * 68 + 64 * 196 + 192) * 4;   // 68352
    const int GRU_SMEM  = (64 * 128 + 64 * 64 + 2 * 192) * 4; // 50688
    const int ATTN_SMEM = (64*80 + 80 + 80*40 + 40 + 40 + 64 + 8*64 + 8*80 + 8*40 + 200 + 32) * 4; // 40992

    cudaFuncSetAttribute(proj_kernel<0>, cudaFuncAttributeMaxDynamicSharedMemorySize, PROJ_SMEM);
    cudaFuncSetAttribute(proj_kernel<1>, cudaFuncAttributeMaxDynamicSharedMemorySize, PROJ_SMEM);
    cudaFuncSetAttribute(gru_kernel<true>,  cudaFuncAttributeMaxDynamicSharedMemorySize, GRU_SMEM);
    cudaFuncSetAttribute(gru_kernel<false>, cudaFuncAttributeMaxDynamicSharedMemorySize, GRU_SMEM);
    cudaFuncSetAttribute(attn_kernel, cudaFuncAttributeMaxDynamicSharedMemorySize, ATTN_SMEM);

    // 1) input projections for GRU1 (gathered embeddings)
    proj_kernel<0><<<BT / 64, 256, PROJ_SMEM>>>(item_emb, hist_i, nullptr,
                                                g1_Wg, g1_bg, g1_Wc, g1_bc, xg, xc);
    // 2) GRU1 recurrence -> rnn1
    gru_kernel<true><<<B / 2, 256, GRU_SMEM>>>(xg, xc, mask, g1_Ug, g1_Uc, rnn1);
    // 3) DIN attention -> alpha
    attn_kernel<<<B, 256, ATTN_SMEM>>>(ii, item_emb, rnn1, mask,
                                       Wa1, ba1, Wa2, ba2, Wa3, ba3, alpha);
    // 4) projections for GRU2 (rnn1 * alpha)
    proj_kernel<1><<<BT / 64, 256, PROJ_SMEM>>>(rnn1, nullptr, alpha,
                                                g2_Wg, g2_bg, g2_Wc, g2_bc, xg, xc);
    // 5) GRU2 recurrence -> final2 only
    gru_kernel<false><<<B / 2, 256, GRU_SMEM>>>(xg, xc, mask, g2_Ug, g2_Uc, final2);
    // 6) FCN head (computes hist_sum internally) -> logits
    fcn_kernel<<<B, 128>>>(u, ii, hist_i, item_emb, user_emb, final2,
                           W1, b1, p1, W2, b2, p2, W3, b3, out);
}

// round 3
// speedup vs baseline: 1.4984x; 1.4965x over previous
#include <cuda_runtime.h>
#include <math.h>
#include <float.h>

#define B 4096
#define T 200
#define BT (B*T)
#define GR 10   // batch rows per GRU block

// ---------------- scratch (device globals: no allocs allowed) ----------------
__device__ float g_xg[(size_t)BT * 128];   // gate input projections (reused GRU1/GRU2)
__device__ float g_xc[(size_t)BT * 64];    // candidate input projections (reused)
__device__ float g_rnn1[(size_t)BT * 64];  // GRU1 states
__device__ float g_alpha[BT];              // attention weights
__device__ float g_final2[B * 64];         // GRU2 final state

__device__ __forceinline__ float sigmoidf_fast(float x) {
    return 1.0f / (1.0f + __expf(-x));
}

// ======================================================================
// Projection kernel: C[64 rows x 192 cols] = A[64x64] @ [Wg | Wc] + bias
// MODE 0: A rows gathered from item_emb via hist_i
// MODE 1: A rows = rnn1 rows scaled by alpha (att_in = rnn1 * alpha)
// ======================================================================
template<int MODE>
__global__ void proj_kernel(const float* __restrict__ src,
                            const int*   __restrict__ hist_i,
                            const float* __restrict__ alpha,
                            const float* __restrict__ Wg,        // [64,128]
                            const float* __restrict__ bg,        // [128]
                            const float* __restrict__ Wc,        // [64,64]
                            const float* __restrict__ bc,        // [64]
                            float* __restrict__ xg,              // [BT,128]
                            float* __restrict__ xc)              // [BT,64]
{
    extern __shared__ float sm[];
    float* As = sm;                 // [64][68] (A transposed: As[k][r])
    float* Ws = sm + 64 * 68;       // [64][196]
    float* bs = Ws + 64 * 196;      // [192]

    const int tid = threadIdx.x;
    const int m0 = blockIdx.x * 64;

    for (int idx = tid; idx < 64 * 128; idx += 256) {
        int k = idx >> 7, c = idx & 127;
        Ws[k * 196 + c] = Wg[idx];
    }
    for (int idx = tid; idx < 64 * 64; idx += 256) {
        int k = idx >> 6, c = idx & 63;
        Ws[k * 196 + 128 + c] = Wc[idx];
    }
    if (tid < 128) bs[tid] = bg[tid];
    else if (tid < 192) bs[tid] = bc[tid - 128];

    {
        int r = tid >> 2;
        int k0 = (tid & 3) << 4;
        const float* srow;
        float scale = 1.0f;
        if (MODE == 0) {
            int ix = hist_i[m0 + r];
            srow = src + (size_t)ix * 64;
        } else {
            srow = src + (size_t)(m0 + r) * 64;
            scale = alpha[m0 + r];
        }
#pragma unroll
        for (int i = 0; i < 4; i++) {
            float4 v = *(const float4*)(srow + k0 + i * 4);
            As[(k0 + i * 4 + 0) * 68 + r] = v.x * scale;
            As[(k0 + i * 4 + 1) * 68 + r] = v.y * scale;
            As[(k0 + i * 4 + 2) * 68 + r] = v.z * scale;
            As[(k0 + i * 4 + 3) * 68 + r] = v.w * scale;
        }
    }
    __syncthreads();

    const int tx = tid & 31;
    const int ty = tid >> 5;

    float acc[8][6];
#pragma unroll
    for (int i = 0; i < 8; i++)
#pragma unroll
        for (int j = 0; j < 6; j++) acc[i][j] = 0.0f;

#pragma unroll 16
    for (int k = 0; k < 64; k++) {
        float4 a0 = *(const float4*)(As + k * 68 + ty * 8);
        float4 a1 = *(const float4*)(As + k * 68 + ty * 8 + 4);
        float av[8] = {a0.x, a0.y, a0.z, a0.w, a1.x, a1.y, a1.z, a1.w};
        const float* wrow = Ws + k * 196 + tx * 6;
        float2 w0 = *(const float2*)(wrow);
        float2 w1 = *(const float2*)(wrow + 2);
        float2 w2 = *(const float2*)(wrow + 4);
        float bv[6] = {w0.x, w0.y, w1.x, w1.y, w2.x, w2.y};
#pragma unroll
        for (int i = 0; i < 8; i++)
#pragma unroll
            for (int j = 0; j < 6; j++)
                acc[i][j] = fmaf(av[i], bv[j], acc[i][j]);
    }

#pragma unroll
    for (int i = 0; i < 8; i++) {
        int m = m0 + ty * 8 + i;
#pragma unroll
        for (int j = 0; j < 6; j++) {
            int col = tx * 6 + j;
            float v = acc[i][j] + bs[col];
            if (col < 128) xg[(size_t)m * 128 + col] = v;
            else           xc[(size_t)m * 64 + (col - 128)] = v;
        }
    }
}

// ======================================================================
// GRU recurrence v2: 128 threads process GR batch rows.
// Weights transposed + padded in smem so each thread does vectorized
// LDS.128 of its column's weights once per k4 and applies to GR rows.
// ======================================================================
template<bool STORE_ALL>
__global__ void __launch_bounds__(128) gru_kernel(
                           const float* __restrict__ xg,
                           const float* __restrict__ xc,
                           const float* __restrict__ mask,
                           const float* __restrict__ Ug,  // [64,128]
                           const float* __restrict__ Uc,  // [64,64]
                           float* __restrict__ out)       // [B,T,64] or [B,64]
{
    extern __shared__ float sm[];
    float* UgsT = sm;                    // [128][68]  UgsT[j*68+k] = Ug[k*128+j]
    float* UcsT = UgsT + 128 * 68;       // [64][68]
    float* hs   = UcsT + 64 * 68;        // [GR][64]
    float* rhs  = hs + GR * 64;          // [GR][64]
    float* zs   = rhs + GR * 64;         // [GR][64]

    const int j = threadIdx.x;           // 0..127
    const int b0 = blockIdx.x * GR;

    for (int idx = j; idx < 128 * 64; idx += 128) {
        int k = idx >> 7, jj = idx & 127;
        UgsT[jj * 68 + k] = Ug[idx];
    }
    for (int idx = j; idx < 64 * 64; idx += 128) {
        int k = idx >> 6, jj = idx & 63;
        UcsT[jj * 68 + k] = Uc[idx];
    }
    for (int idx = j; idx < GR * 64; idx += 128) hs[idx] = 0.0f;

    int br[GR];
    bool val[GR];
#pragma unroll
    for (int r = 0; r < GR; r++) {
        int b = b0 + r;
        val[r] = (b < B);
        br[r] = val[r] ? b : (B - 1);
    }
    __syncthreads();

    float xgv[GR];
#pragma unroll
    for (int r = 0; r < GR; r++)
        xgv[r] = xg[(size_t)br[r] * T * 128 + j];

    for (int t = 0; t < T; t++) {
        // ---- gate phase (all 128 threads) ----
        float acc[GR];
#pragma unroll
        for (int r = 0; r < GR; r++) acc[r] = xgv[r];

#pragma unroll 4
        for (int k4 = 0; k4 < 16; k4++) {
            float4 w = *(const float4*)(UgsT + j * 68 + 4 * k4);
#pragma unroll
            for (int r = 0; r < GR; r++) {
                float4 h4 = *(const float4*)(hs + r * 64 + 4 * k4);
                acc[r] = fmaf(h4.x, w.x, acc[r]);
                acc[r] = fmaf(h4.y, w.y, acc[r]);
                acc[r] = fmaf(h4.z, w.z, acc[r]);
                acc[r] = fmaf(h4.w, w.w, acc[r]);
            }
        }

        // prefetch next xg
        if (t + 1 < T) {
#pragma unroll
            for (int r = 0; r < GR; r++)
                xgv[r] = xg[(size_t)br[r] * T * 128 + (t + 1) * 128 + j];
        }

#pragma unroll
        for (int r = 0; r < GR; r++) {
            float g = sigmoidf_fast(acc[r]);
            if (j < 64) rhs[r * 64 + j] = g * hs[r * 64 + j];
            else        zs[r * 64 + (j - 64)] = g;
        }
        __syncthreads();

        // ---- candidate phase (threads 0..63) ----
        if (j < 64) {
            float cacc[GR];
#pragma unroll
            for (int r = 0; r < GR; r++)
                cacc[r] = xc[(size_t)br[r] * T * 64 + t * 64 + j];

#pragma unroll 4
            for (int k4 = 0; k4 < 16; k4++) {
                float4 w = *(const float4*)(UcsT + j * 68 + 4 * k4);
#pragma unroll
                for (int r = 0; r < GR; r++) {
                    float4 rh4 = *(const float4*)(rhs + r * 64 + 4 * k4);
                    cacc[r] = fmaf(rh4.x, w.x, cacc[r]);
                    cacc[r] = fmaf(rh4.y, w.y, cacc[r]);
                    cacc[r] = fmaf(rh4.z, w.z, cacc[r]);
                    cacc[r] = fmaf(rh4.w, w.w, cacc[r]);
                }
            }
#pragma unroll
            for (int r = 0; r < GR; r++) {
                float c = tanhf(cacc[r]);
                float z = zs[r * 64 + j];
                float h = hs[r * 64 + j];
                float hn = fmaf(z, h - c, c);        // z*h + (1-z)*c
                float m = mask[(size_t)br[r] * T + t];
                float hnew = fmaf(m, hn - h, h);
                hs[r * 64 + j] = hnew;
                if (STORE_ALL && val[r])
                    out[(size_t)br[r] * T * 64 + t * 64 + j] = hnew;
            }
        }
        __syncthreads();
    }

    if (!STORE_ALL && j < 64) {
#pragma unroll
        for (int r = 0; r < GR; r++)
            if (val[r]) out[(size_t)br[r] * 64 + j] = hs[r * 64 + j];
    }
}

// ======================================================================
// DIN attention v2: register-tiled layers, 320 threads, chunks of 32 t.
// Folded layer1: base[c] = ba1 + q@(W0+W2); Weff[k][c] = (W1-W2)[k][c] + q_k*W3[k][c]
// ======================================================================
__global__ void __launch_bounds__(320) attn_kernel(
                            const int*   __restrict__ item_i,
                            const float* __restrict__ item_emb,
                            const float* __restrict__ rnn1,
                            const float* __restrict__ mask,
                            const float* __restrict__ Wa1, const float* __restrict__ ba1,
                            const float* __restrict__ Wa2, const float* __restrict__ ba2,
                            const float* __restrict__ Wa3, const float* __restrict__ ba3,
                            float* __restrict__ alpha)
{
    extern __shared__ float sm[];
    float* Weff = sm;                  // [64][80]
    float* base = Weff + 64 * 80;      // [80]
    float* Wa2s = base + 80;           // [80][40]
    float* ba2s = Wa2s + 80 * 40;      // [40]
    float* Wa3s = ba2s + 40;           // [40]
    float* qs   = Wa3s + 40;           // [64]
    float* Ks   = qs + 64;             // [32][68] padded
    float* d1s  = Ks + 32 * 68;        // [32][80]
    float* d2s  = d1s + 32 * 80;       // [32][40]
    float* sc   = d2s + 32 * 40;       // [224]
    float* red  = sc + 224;            // [16]

    const int b = blockIdx.x;
    const int tid = threadIdx.x;

    // layer1 tiling: 16 t-tiles x 20 c-tiles; tile = 2t x 4c
    const int l1_t0 = (tid / 20) * 2;
    const int l1_c0 = (tid % 20) * 4;
    // layer2 tiling (tid<160): 16 t-tiles x 10 c-tiles; tile = 2t x 4c
    const int l2_t0 = (tid / 10) * 2;
    const int l2_c0 = (tid % 10) * 4;

    if (tid < 64) qs[tid] = item_emb[(size_t)item_i[b] * 64 + tid];
    __syncthreads();

    if (tid < 80) {
        int c = tid;
        float acc = ba1[c];
#pragma unroll 8
        for (int k = 0; k < 64; k++)
            acc = fmaf(qs[k], Wa1[k * 80 + c] + Wa1[(128 + k) * 80 + c], acc);
        base[c] = acc;
    }
    for (int idx = tid; idx < 64 * 80; idx += 320) {
        int k = idx / 80, c = idx - k * 80;
        Weff[idx] = Wa1[(64 + k) * 80 + c] - Wa1[(128 + k) * 80 + c]
                  + qs[k] * Wa1[(192 + k) * 80 + c];
    }
    for (int idx = tid; idx < 80 * 40; idx += 320) Wa2s[idx] = Wa2[idx];
    if (tid < 40) { ba2s[tid] = ba2[tid]; Wa3s[tid] = Wa3[tid]; }
    __syncthreads();

    const float ba3v = ba3[0];

    for (int cc = 0; cc < 7; cc++) {
        const int tt0 = cc * 32;

        // load K chunk (clamped at T-1 for tail)
        for (int idx = tid; idx < 512; idx += 320) {
            int tl = idx >> 4, k4 = idx & 15;
            int tg = tt0 + tl; if (tg > T - 1) tg = T - 1;
            float4 v = *(const float4*)(rnn1 + ((size_t)b * T + tg) * 64 + 4 * k4);
            *(float4*)(Ks + tl * 68 + 4 * k4) = v;
        }
        __syncthreads();

        // ---- layer 1: [32t x 80c] ----
        {
            float4 bse = *(const float4*)(base + l1_c0);
            float a00 = bse.x, a01 = bse.y, a02 = bse.z, a03 = bse.w;
            float a10 = bse.x, a11 = bse.y, a12 = bse.z, a13 = bse.w;
#pragma unroll 4
            for (int k4 = 0; k4 < 16; k4++) {
                float4 k0 = *(const float4*)(Ks + l1_t0 * 68 + 4 * k4);
                float4 k1 = *(const float4*)(Ks + (l1_t0 + 1) * 68 + 4 * k4);
                const float kk0[4] = {k0.x, k0.y, k0.z, k0.w};
                const float kk1[4] = {k1.x, k1.y, k1.z, k1.w};
#pragma unroll
                for (int kk = 0; kk < 4; kk++) {
                    float4 w = *(const float4*)(Weff + (4 * k4 + kk) * 80 + l1_c0);
                    a00 = fmaf(kk0[kk], w.x, a00); a01 = fmaf(kk0[kk], w.y, a01);
                    a02 = fmaf(kk0[kk], w.z, a02); a03 = fmaf(kk0[kk], w.w, a03);
                    a10 = fmaf(kk1[kk], w.x, a10); a11 = fmaf(kk1[kk], w.y, a11);
                    a12 = fmaf(kk1[kk], w.z, a12); a13 = fmaf(kk1[kk], w.w, a13);
                }
            }
            float4 o0 = make_float4(sigmoidf_fast(a00), sigmoidf_fast(a01),
                                    sigmoidf_fast(a02), sigmoidf_fast(a03));
            float4 o1 = make_float4(sigmoidf_fast(a10), sigmoidf_fast(a11),
                                    sigmoidf_fast(a12), sigmoidf_fast(a13));
            *(float4*)(d1s + l1_t0 * 80 + l1_c0) = o0;
            *(float4*)(d1s + (l1_t0 + 1) * 80 + l1_c0) = o1;
        }
        __syncthreads();

        // ---- layer 2: [32t x 40c] ----
        if (tid < 160) {
            float4 bse = *(const float4*)(ba2s + l2_c0);
            float a00 = bse.x, a01 = bse.y, a02 = bse.z, a03 = bse.w;
            float a10 = bse.x, a11 = bse.y, a12 = bse.z, a13 = bse.w;
#pragma unroll 4
            for (int k4 = 0; k4 < 20; k4++) {
                float4 d0 = *(const float4*)(d1s + l2_t0 * 80 + 4 * k4);
                float4 d1 = *(const float4*)(d1s + (l2_t0 + 1) * 80 + 4 * k4);
                const float dd0[4] = {d0.x, d0.y, d0.z, d0.w};
                const float dd1[4] = {d1.x, d1.y, d1.z, d1.w};
#pragma unroll
                for (int kk = 0; kk < 4; kk++) {
                    float4 w = *(const float4*)(Wa2s + (4 * k4 + kk) * 40 + l2_c0);
                    a00 = fmaf(dd0[kk], w.x, a00); a01 = fmaf(dd0[kk], w.y, a01);
                    a02 = fmaf(dd0[kk], w.z, a02); a03 = fmaf(dd0[kk], w.w, a03);
                    a10 = fmaf(dd1[kk], w.x, a10); a11 = fmaf(dd1[kk], w.y, a11);
                    a12 = fmaf(dd1[kk], w.z, a12); a13 = fmaf(dd1[kk], w.w, a13);
                }
            }
            float4 o0 = make_float4(sigmoidf_fast(a00), sigmoidf_fast(a01),
                                    sigmoidf_fast(a02), sigmoidf_fast(a03));
            float4 o1 = make_float4(sigmoidf_fast(a10), sigmoidf_fast(a11),
                                    sigmoidf_fast(a12), sigmoidf_fast(a13));
            *(float4*)(d2s + l2_t0 * 40 + l2_c0) = o0;
            *(float4*)(d2s + (l2_t0 + 1) * 40 + l2_c0) = o1;
        }
        __syncthreads();

        // ---- layer 3: 32 scores ----
        if (tid < 32) {
            float acc = ba3v;
#pragma unroll
            for (int k4 = 0; k4 < 10; k4++) {
                float4 d = *(const float4*)(d2s + tid * 40 + 4 * k4);
                float4 w = *(const float4*)(Wa3s + 4 * k4);
                acc = fmaf(d.x, w.x, acc); acc = fmaf(d.y, w.y, acc);
                acc = fmaf(d.z, w.z, acc); acc = fmaf(d.w, w.w, acc);
            }
            int tg = tt0 + tid;
            if (tg < T) {
                float m = mask[(size_t)b * T + tg];
                sc[tg] = (m > 0.0f) ? acc : -1e9f;
            }
        }
        __syncthreads();
    }

    // ---- masked softmax over T=200 (10 warps) ----
    float v = (tid < T) ? sc[tid] : -FLT_MAX;
#pragma unroll
    for (int o = 16; o > 0; o >>= 1) v = fmaxf(v, __shfl_xor_sync(0xffffffffu, v, o));
    if ((tid & 31) == 0) red[tid >> 5] = v;
    __syncthreads();
    if (tid == 0) {
        float mx = red[0];
#pragma unroll
        for (int w = 1; w < 10; w++) mx = fmaxf(mx, red[w]);
        red[12] = mx;
    }
    __syncthreads();
    float mx = red[12];

    float e = (tid < T) ? __expf(sc[tid] - mx) : 0.0f;
    float s = e;
#pragma unroll
    for (int o = 16; o > 0; o >>= 1) s += __shfl_xor_sync(0xffffffffu, s, o);
    __syncthreads();
    if ((tid & 31) == 0) red[tid >> 5] = s;
    __syncthreads();
    if (tid == 0) {
        float sum = 0.0f;
#pragma unroll
        for (int w = 0; w < 10; w++) sum += red[w];
        red[13] = 1.0f / sum;
    }
    __syncthreads();
    if (tid < T) alpha[(size_t)b * T + tid] = e * red[13];
}

// ======================================================================
// FCN head + hist_sum. One block (128 thr) per batch row.
// ======================================================================
__global__ void fcn_kernel(const int* __restrict__ u, const int* __restrict__ ii,
                           const int* __restrict__ hist_i,
                           const float* __restrict__ item_emb,
                           const float* __restrict__ user_emb,
                           const float* __restrict__ final2,
                           const float* __restrict__ W1, const float* __restrict__ b1,
                           const float* __restrict__ p1,
                           const float* __restrict__ W2, const float* __restrict__ b2,
                           const float* __restrict__ p2,
                           const float* __restrict__ W3, const float* __restrict__ b3,
                           float* __restrict__ out)
{
    __shared__ float xs[320];
    __shared__ float h1s[128];
    __shared__ float h2s[40];

    const int b = blockIdx.x;
    const int tid = threadIdx.x;

    if (tid < 64) {
        const int* hi = hist_i + (size_t)b * T;
        float s0 = 0.f, s1 = 0.f, s2 = 0.f, s3 = 0.f;
        for (int t = 0; t < T; t += 4) {
            s0 += item_emb[(size_t)hi[t]     * 64 + tid];
            s1 += item_emb[(size_t)hi[t + 1] * 64 + tid];
            s2 += item_emb[(size_t)hi[t + 2] * 64 + tid];
            s3 += item_emb[(size_t)hi[t + 3] * 64 + tid];
        }
        xs[128 + tid] = (s0 + s1) + (s2 + s3);
    } else {
        int j = tid - 64;
        xs[j]       = user_emb[(size_t)u[b]  * 64 + j];
        xs[64 + j]  = item_emb[(size_t)ii[b] * 64 + j];
        xs[256 + j] = final2[(size_t)b * 64 + j];
    }
    __syncthreads();
    if (tid < 64) xs[192 + tid] = xs[64 + tid] * xs[128 + tid];
    __syncthreads();

    {
        float a0 = b1[tid], a1 = 0.0f;
#pragma unroll 8
        for (int k = 0; k < 320; k += 2) {
            a0 = fmaf(xs[k],     W1[k * 128 + tid],       a0);
            a1 = fmaf(xs[k + 1], W1[(k + 1) * 128 + tid], a1);
        }
        float h = a0 + a1;
        h1s[tid] = (h >= 0.0f) ? h : p1[tid] * h;
    }
    __syncthreads();

    if (tid < 40) {
        float a0 = b2[tid], a1 = 0.0f;
#pragma unroll 16
        for (int k = 0; k < 128; k += 2) {
            a0 = fmaf(h1s[k],     W2[k * 40 + tid],       a0);
            a1 = fmaf(h1s[k + 1], W2[(k + 1) * 40 + tid], a1);
        }
        float h = a0 + a1;
        h2s[tid] = (h >= 0.0f) ? h : p2[tid] * h;
    }
    __syncthreads();

    if (tid == 0) {
        float acc = b3[0];
#pragma unroll
        for (int k = 0; k < 40; k++) acc = fmaf(h2s[k], W3[k], acc);
        out[b] = acc;
    }
}

// ======================================================================
extern "C" void kernel_launch(void* const* d_in, const int* in_sizes, int n_in,
                              void* d_out, int out_size)
{
    const int*   u        = (const int*)d_in[0];
    const int*   ii       = (const int*)d_in[1];
    const int*   hist_i   = (const int*)d_in[2];
    const float* mask     = (const float*)d_in[3];
    const float* item_emb = (const float*)d_in[4];
    const float* user_emb = (const float*)d_in[5];
    const float* g1_Wg = (const float*)d_in[6];
    const float* g1_Ug = (const float*)d_in[7];
    const float* g1_bg = (const float*)d_in[8];
    const float* g1_Wc = (const float*)d_in[9];
    const float* g1_Uc = (const float*)d_in[10];
    const float* g1_bc = (const float*)d_in[11];
    const float* Wa1 = (const float*)d_in[12];
    const float* ba1 = (const float*)d_in[13];
    const float* Wa2 = (const float*)d_in[14];
    const float* ba2 = (const float*)d_in[15];
    const float* Wa3 = (const float*)d_in[16];
    const float* ba3 = (const float*)d_in[17];
    const float* g2_Wg = (const float*)d_in[18];
    const float* g2_Ug = (const float*)d_in[19];
    const float* g2_bg = (const float*)d_in[20];
    const float* g2_Wc = (const float*)d_in[21];
    const float* g2_Uc = (const float*)d_in[22];
    const float* g2_bc = (const float*)d_in[23];
    const float* W1 = (const float*)d_in[24];
    const float* b1 = (const float*)d_in[25];
    const float* p1 = (const float*)d_in[26];
    const float* W2 = (const float*)d_in[27];
    const float* b2 = (const float*)d_in[28];
    const float* p2 = (const float*)d_in[29];
    const float* W3 = (const float*)d_in[30];
    const float* b3 = (const float*)d_in[31];
    float* out = (float*)d_out;

    float *xg, *xc, *rnn1, *alpha, *final2;
    cudaGetSymbolAddress((void**)&xg,     g_xg);
    cudaGetSymbolAddress((void**)&xc,     g_xc);
    cudaGetSymbolAddress((void**)&rnn1,   g_rnn1);
    cudaGetSymbolAddress((void**)&alpha,  g_alpha);
    cudaGetSymbolAddress((void**)&final2, g_final2);

    const int PROJ_SMEM = (64 * 68 + 64 * 196 + 192) * 4;            // 68352
    const int GRU_SMEM  = (128 * 68 + 64 * 68 + 3 * GR * 64) * 4;    // 59904
    const int ATTN_SMEM = (64*80 + 80 + 80*40 + 40 + 40 + 64
                         + 32*68 + 32*80 + 32*40 + 224 + 16) * 4;    // 59200

    cudaFuncSetAttribute(proj_kernel<0>, cudaFuncAttributeMaxDynamicSharedMemorySize, PROJ_SMEM);
    cudaFuncSetAttribute(proj_kernel<1>, cudaFuncAttributeMaxDynamicSharedMemorySize, PROJ_SMEM);
    cudaFuncSetAttribute(gru_kernel<true>,  cudaFuncAttributeMaxDynamicSharedMemorySize, GRU_SMEM);
    cudaFuncSetAttribute(gru_kernel<false>, cudaFuncAttributeMaxDynamicSharedMemorySize, GRU_SMEM);
    cudaFuncSetAttribute(attn_kernel, cudaFuncAttributeMaxDynamicSharedMemorySize, ATTN_SMEM);

    const int GRU_GRID = (B + GR - 1) / GR;   // 410

    // 1) input projections for GRU1 (gathered embeddings)
    proj_kernel<0><<<BT / 64, 256, PROJ_SMEM>>>(item_emb, hist_i, nullptr,
                                                g1_Wg, g1_bg, g1_Wc, g1_bc, xg, xc);
    // 2) GRU1 recurrence -> rnn1
    gru_kernel<true><<<GRU_GRID, 128, GRU_SMEM>>>(xg, xc, mask, g1_Ug, g1_Uc, rnn1);
    // 3) DIN attention -> alpha
    attn_kernel<<<B, 320, ATTN_SMEM>>>(ii, item_emb, rnn1, mask,
                                       Wa1, ba1, Wa2, ba2, Wa3, ba3, alpha);
    // 4) projections for GRU2 (rnn1 * alpha)
    proj_kernel<1><<<BT / 64, 256, PROJ_SMEM>>>(rnn1, nullptr, alpha,
                                                g2_Wg, g2_bg, g2_Wc, g2_bc, xg, xc);
    // 5) GRU2 recurrence -> final2 only
    gru_kernel<false><<<GRU_GRID, 128, GRU_SMEM>>>(xg, xc, mask, g2_Ug, g2_Uc, final2);
    // 6) FCN head -> logits
    fcn_kernel<<<B, 128>>>(u, ii, hist_i, item_emb, user_emb, final2,
                           W1, b1, p1, W2, b2, p2, W3, b3, out);
}

// round 6
// speedup vs baseline: 1.8520x; 1.2360x over previous
#include <cuda_runtime.h>
#include <cuda_bf16.h>
#include <math.h>
#include <float.h>
#include <cstdint>

#define B 4096
#define T 200
#define BT (B*T)
#define GR 10   // batch rows per GRU block

// ---------------- scratch (device globals: no allocs allowed) ----------------
__device__ float g_xg[(size_t)BT * 128];
__device__ float g_xc[(size_t)BT * 64];
__device__ float g_rnn1[(size_t)BT * 64];
__device__ float g_alpha[BT];
__device__ float g_final2[B * 64];
// split-bf16 weights for the two projection GEMMs: layout [n(192)][k(64)]
__device__ __nv_bfloat16 g_bh1[192 * 64];
__device__ __nv_bfloat16 g_bl1[192 * 64];
__device__ __nv_bfloat16 g_bh2[192 * 64];
__device__ __nv_bfloat16 g_bl2[192 * 64];

__device__ __forceinline__ float sigmoidf_fast(float x) {
    return 1.0f / (1.0f + __expf(-x));
}

__device__ __forceinline__ uint32_t smem_u32(const void* p) {
    uint32_t a;
    asm("{ .reg .u64 t; cvta.to.shared.u64 t, %1; cvt.u32.u64 %0, t; }" : "=r"(a) : "l"(p));
    return a;
}
__device__ __forceinline__ void ldsm_x4(uint32_t& r0, uint32_t& r1, uint32_t& r2, uint32_t& r3,
                                        uint32_t addr) {
    asm volatile("ldmatrix.sync.aligned.m8n8.x4.shared.b16 {%0,%1,%2,%3}, [%4];"
                 : "=r"(r0), "=r"(r1), "=r"(r2), "=r"(r3) : "r"(addr));
}
__device__ __forceinline__ void mma16816(float* c, const uint32_t* a, uint32_t b0, uint32_t b1) {
    asm volatile("mma.sync.aligned.m16n8k16.row.col.f32.bf16.bf16.f32 "
                 "{%0,%1,%2,%3}, {%4,%5,%6,%7}, {%8,%9}, {%0,%1,%2,%3};"
                 : "+f"(c[0]), "+f"(c[1]), "+f"(c[2]), "+f"(c[3])
                 : "r"(a[0]), "r"(a[1]), "r"(a[2]), "r"(a[3]), "r"(b0), "r"(b1));
}

// ======================================================================
// Weight split prep: W[64,128]|[64,64] fp32 -> Bhi/Blo [n=192][k=64] bf16
// ======================================================================
__global__ void wsplit_kernel(const float* __restrict__ Wg, const float* __restrict__ Wc,
                              __nv_bfloat16* __restrict__ Bhi, __nv_bfloat16* __restrict__ Blo)
{
    int idx = blockIdx.x * 256 + threadIdx.x;
    if (idx >= 192 * 64) return;
    int n = idx >> 6, k = idx & 63;
    float w = (n < 128) ? Wg[k * 128 + n] : Wc[k * 64 + (n - 128)];
    __nv_bfloat16 hi = __float2bfloat16(w);
    __nv_bfloat16 lo = __float2bfloat16(w - __bfloat162float(hi));
    Bhi[idx] = hi;
    Blo[idx] = lo;
}

// ======================================================================
// HMMA projection: per block, D[128 x 192] = A[128x64] @ W + bias
// split-bf16 (3 terms: aH*bH + aH*bL + aL*bH) for ~fp32 precision.
// 256 threads = 8 warps; warp w owns rows [16w,16w+16); N in two halves
// of 96 cols. A,B k-major in smem, 144B row stride (conflict-free ldmatrix).
// ======================================================================
#define PAD_K 72   // bf16 elements per smem row (144 B)
#define PSM_BIAS 0
#define PSM_AHI  768
#define PSM_ALO  (PSM_AHI + 128 * PAD_K * 2)    // +18432
#define PSM_BHI  (PSM_ALO + 128 * PAD_K * 2)
#define PSM_BLO  (PSM_BHI + 192 * PAD_K * 2)    // +27648
#define PSM_TOTAL (PSM_BLO + 192 * PAD_K * 2)   // 92928 bytes

template<int MODE>
__global__ void __launch_bounds__(256, 2) proj_mma_kernel(
        const float* __restrict__ src,        // emb table or rnn1
        const int*   __restrict__ hist_i,     // MODE 0
        const float* __restrict__ alpha,      // MODE 1
        const __nv_bfloat16* __restrict__ Bhi,
        const __nv_bfloat16* __restrict__ Blo,
        const float* __restrict__ bg,         // [128]
        const float* __restrict__ bc,         // [64]
        float* __restrict__ xg,               // [BT,128]
        float* __restrict__ xc)               // [BT,64]
{
    extern __shared__ char smem[];
    const uint32_t sbase = smem_u32(smem);
    const int tid = threadIdx.x;
    const int wid = tid >> 5;
    const int lane = tid & 31;
    const int m0 = blockIdx.x * 128;

    // ---- bias ----
    float* bs = (float*)(smem + PSM_BIAS);
    if (tid < 192) bs[tid] = (tid < 128) ? bg[tid] : bc[tid - 128];

    // ---- B tiles: [n][k] bf16 -> padded smem ----
    // row = 64 bf16 = 128 B = 8 uint4 segments; 192 rows -> 1536 uint4 total.
    {
        const uint4* sh = (const uint4*)Bhi;
        const uint4* sl = (const uint4*)Blo;
#pragma unroll
        for (int i = 0; i < 6; i++) {
            int idx = tid + 256 * i;               // < 1536
            int n = idx >> 3, seg = idx & 7;
            int off = n * (PAD_K * 2) + seg * 16;
            *(uint4*)(smem + PSM_BHI + off) = sh[idx];
            *(uint4*)(smem + PSM_BLO + off) = sl[idx];
        }
    }

    // ---- A tile: 2 threads per row, 32 floats each; fp32 -> hi/lo bf16 ----
    {
        const int r = tid >> 1;
        const int half = tid & 1;
        const float* srow;
        float scale = 1.0f;
        if (MODE == 0) {
            srow = src + (size_t)hist_i[m0 + r] * 64;
        } else {
            srow = src + (size_t)(m0 + r) * 64;
            scale = alpha[m0 + r];
        }
        srow += half * 32;
        const int kb = half * 32;
#pragma unroll
        for (int c = 0; c < 4; c++) {              // 8 elems per chunk
            float4 v0 = *(const float4*)(srow + 8 * c);
            float4 v1 = *(const float4*)(srow + 8 * c + 4);
            float vv[8] = {v0.x, v0.y, v0.z, v0.w, v1.x, v1.y, v1.z, v1.w};
            __nv_bfloat16 hb[8], lb[8];
#pragma unroll
            for (int e = 0; e < 8; e++) {
                float f = vv[e] * scale;
                hb[e] = __float2bfloat16(f);
                lb[e] = __float2bfloat16(f - __bfloat162float(hb[e]));
            }
            int off = r * (PAD_K * 2) + (kb + 8 * c) * 2;
            *(uint4*)(smem + PSM_AHI + off) = *(uint4*)hb;
            *(uint4*)(smem + PSM_ALO + off) = *(uint4*)lb;
        }
    }
    __syncthreads();

    // per-lane ldmatrix base offsets
    const int arow = wid * 16 + (lane & 15);
    const int acolb = ((lane >> 4) << 3);             // 0 or 8
    const uint32_t a_off = (uint32_t)arow * (PAD_K * 2) + acolb * 2;
    const uint32_t aH_base = sbase + PSM_AHI + a_off;
    const uint32_t aL_base = sbase + PSM_ALO + a_off;

    const int bnrow_l = (lane & 7) + ((lane & 16) >> 1);  // 0..15
    const int bcol_l = (lane & 8);                         // 0 or 8
    const uint32_t b_off_l = (uint32_t)bnrow_l * (PAD_K * 2) + bcol_l * 2;

    const int g = lane >> 2;
    const int tq = lane & 3;

#pragma unroll
    for (int nh = 0; nh < 2; nh++) {
        const uint32_t bH_base = sbase + PSM_BHI + b_off_l + (uint32_t)nh * 96 * (PAD_K * 2);
        const uint32_t bL_base = sbase + PSM_BLO + b_off_l + (uint32_t)nh * 96 * (PAD_K * 2);

        float acc[12][4];
#pragma unroll
        for (int i = 0; i < 12; i++)
#pragma unroll
            for (int q = 0; q < 4; q++) acc[i][q] = 0.0f;

#pragma unroll
        for (int ks = 0; ks < 4; ks++) {
            uint32_t aH[4], aL[4];
            ldsm_x4(aH[0], aH[1], aH[2], aH[3], aH_base + ks * 32);
            ldsm_x4(aL[0], aL[1], aL[2], aL[3], aL_base + ks * 32);
#pragma unroll
            for (int np = 0; np < 6; np++) {
                uint32_t bh0, bh1, bh2, bh3;
                ldsm_x4(bh0, bh1, bh2, bh3,
                        bH_base + (uint32_t)np * 16 * (PAD_K * 2) + ks * 32);
                mma16816(acc[2 * np],     aH, bh0, bh1);
                mma16816(acc[2 * np + 1], aH, bh2, bh3);
                mma16816(acc[2 * np],     aL, bh0, bh1);
                mma16816(acc[2 * np + 1], aL, bh2, bh3);
                uint32_t bl0, bl1, bl2, bl3;
                ldsm_x4(bl0, bl1, bl2, bl3,
                        bL_base + (uint32_t)np * 16 * (PAD_K * 2) + ks * 32);
                mma16816(acc[2 * np],     aH, bl0, bl1);
                mma16816(acc[2 * np + 1], aH, bl2, bl3);
            }
        }

        // ---- epilogue ----
        const int r0 = m0 + wid * 16 + g;
        const int r1 = r0 + 8;
#pragma unroll
        for (int nt = 0; nt < 12; nt++) {
            const int n = nh * 96 + nt * 8 + 2 * tq;
            const float bx = bs[n], by = bs[n + 1];
            float2 o0 = make_float2(acc[nt][0] + bx, acc[nt][1] + by);
            float2 o1 = make_float2(acc[nt][2] + bx, acc[nt][3] + by);
            if (n < 128) {
                *(float2*)(xg + (size_t)r0 * 128 + n) = o0;
                *(float2*)(xg + (size_t)r1 * 128 + n) = o1;
            } else {
                *(float2*)(xc + (size_t)r0 * 64 + (n - 128)) = o0;
                *(float2*)(xc + (size_t)r1 * 64 + (n - 128)) = o1;
            }
        }
    }
}

// ======================================================================
// GRU recurrence: 128 threads process GR batch rows (unchanged).
// ======================================================================
template<bool STORE_ALL>
__global__ void __launch_bounds__(128) gru_kernel(
                           const float* __restrict__ xg,
                           const float* __restrict__ xc,
                           const float* __restrict__ mask,
                           const float* __restrict__ Ug,  // [64,128]
                           const float* __restrict__ Uc,  // [64,64]
                           float* __restrict__ out)
{
    extern __shared__ float sm[];
    float* UgsT = sm;
    float* UcsT = UgsT + 128 * 68;
    float* hs   = UcsT + 64 * 68;
    float* rhs  = hs + GR * 64;
    float* zs   = rhs + GR * 64;

    const int j = threadIdx.x;
    const int b0 = blockIdx.x * GR;

    for (int idx = j; idx < 128 * 64; idx += 128) {
        int k = idx >> 7, jj = idx & 127;
        UgsT[jj * 68 + k] = Ug[idx];
    }
    for (int idx = j; idx < 64 * 64; idx += 128) {
        int k = idx >> 6, jj = idx & 63;
        UcsT[jj * 68 + k] = Uc[idx];
    }
    for (int idx = j; idx < GR * 64; idx += 128) hs[idx] = 0.0f;

    int br[GR];
    bool val[GR];
#pragma unroll
    for (int r = 0; r < GR; r++) {
        int b = b0 + r;
        val[r] = (b < B);
        br[r] = val[r] ? b : (B - 1);
    }
    __syncthreads();

    float xgv[GR];
#pragma unroll
    for (int r = 0; r < GR; r++)
        xgv[r] = xg[(size_t)br[r] * T * 128 + j];

    for (int t = 0; t < T; t++) {
        float acc[GR];
#pragma unroll
        for (int r = 0; r < GR; r++) acc[r] = xgv[r];

#pragma unroll 4
        for (int k4 = 0; k4 < 16; k4++) {
            float4 w = *(const float4*)(UgsT + j * 68 + 4 * k4);
#pragma unroll
            for (int r = 0; r < GR; r++) {
                float4 h4 = *(const float4*)(hs + r * 64 + 4 * k4);
                acc[r] = fmaf(h4.x, w.x, acc[r]);
                acc[r] = fmaf(h4.y, w.y, acc[r]);
                acc[r] = fmaf(h4.z, w.z, acc[r]);
                acc[r] = fmaf(h4.w, w.w, acc[r]);
            }
        }

        if (t + 1 < T) {
#pragma unroll
            for (int r = 0; r < GR; r++)
                xgv[r] = xg[(size_t)br[r] * T * 128 + (t + 1) * 128 + j];
        }

#pragma unroll
        for (int r = 0; r < GR; r++) {
            float g = sigmoidf_fast(acc[r]);
            if (j < 64) rhs[r * 64 + j] = g * hs[r * 64 + j];
            else        zs[r * 64 + (j - 64)] = g;
        }
        __syncthreads();

        if (j < 64) {
            float cacc[GR];
#pragma unroll
            for (int r = 0; r < GR; r++)
                cacc[r] = xc[(size_t)br[r] * T * 64 + t * 64 + j];

#pragma unroll 4
            for (int k4 = 0; k4 < 16; k4++) {
                float4 w = *(const float4*)(UcsT + j * 68 + 4 * k4);
#pragma unroll
                for (int r = 0; r < GR; r++) {
                    float4 rh4 = *(const float4*)(rhs + r * 64 + 4 * k4);
                    cacc[r] = fmaf(rh4.x, w.x, cacc[r]);
                    cacc[r] = fmaf(rh4.y, w.y, cacc[r]);
                    cacc[r] = fmaf(rh4.z, w.z, cacc[r]);
                    cacc[r] = fmaf(rh4.w, w.w, cacc[r]);
                }
            }
#pragma unroll
            for (int r = 0; r < GR; r++) {
                float c = tanhf(cacc[r]);
                float z = zs[r * 64 + j];
                float h = hs[r * 64 + j];
                float hn = fmaf(z, h - c, c);
                float m = mask[(size_t)br[r] * T + t];
                float hnew = fmaf(m, hn - h, h);
                hs[r * 64 + j] = hnew;
                if (STORE_ALL && val[r])
                    out[(size_t)br[r] * T * 64 + t * 64 + j] = hnew;
            }
        }
        __syncthreads();
    }

    if (!STORE_ALL && j < 64) {
#pragma unroll
        for (int r = 0; r < GR; r++)
            if (val[r]) out[(size_t)br[r] * 64 + j] = hs[r * 64 + j];
    }
}

// ======================================================================
// DIN attention (unchanged).
// ======================================================================
__global__ void __launch_bounds__(320) attn_kernel(
                            const int*   __restrict__ item_i,
                            const float* __restrict__ item_emb,
                            const float* __restrict__ rnn1,
                            const float* __restrict__ mask,
                            const float* __restrict__ Wa1, const float* __restrict__ ba1,
                            const float* __restrict__ Wa2, const float* __restrict__ ba2,
                            const float* __restrict__ Wa3, const float* __restrict__ ba3,
                            float* __restrict__ alpha)
{
    extern __shared__ float sm[];
    float* Weff = sm;
    float* base = Weff + 64 * 80;
    float* Wa2s = base + 80;
    float* ba2s = Wa2s + 80 * 40;
    float* Wa3s = ba2s + 40;
    float* qs   = Wa3s + 40;
    float* Ks   = qs + 64;
    float* d1s  = Ks + 32 * 68;
    float* d2s  = d1s + 32 * 80;
    float* sc   = d2s + 32 * 40;
    float* red  = sc + 224;

    const int b = blockIdx.x;
    const int tid = threadIdx.x;

    const int l1_t0 = (tid / 20) * 2;
    const int l1_c0 = (tid % 20) * 4;
    const int l2_t0 = (tid / 10) * 2;
    const int l2_c0 = (tid % 10) * 4;

    if (tid < 64) qs[tid] = item_emb[(size_t)item_i[b] * 64 + tid];
    __syncthreads();

    if (tid < 80) {
        int c = tid;
        float acc = ba1[c];
#pragma unroll 8
        for (int k = 0; k < 64; k++)
            acc = fmaf(qs[k], Wa1[k * 80 + c] + Wa1[(128 + k) * 80 + c], acc);
        base[c] = acc;
    }
    for (int idx = tid; idx < 64 * 80; idx += 320) {
        int k = idx / 80, c = idx - k * 80;
        Weff[idx] = Wa1[(64 + k) * 80 + c] - Wa1[(128 + k) * 80 + c]
                  + qs[k] * Wa1[(192 + k) * 80 + c];
    }
    for (int idx = tid; idx < 80 * 40; idx += 320) Wa2s[idx] = Wa2[idx];
    if (tid < 40) { ba2s[tid] = ba2[tid]; Wa3s[tid] = Wa3[tid]; }
    __syncthreads();

    const float ba3v = ba3[0];

    for (int cc = 0; cc < 7; cc++) {
        const int tt0 = cc * 32;

        for (int idx = tid; idx < 512; idx += 320) {
            int tl = idx >> 4, k4 = idx & 15;
            int tg = tt0 + tl; if (tg > T - 1) tg = T - 1;
            float4 v = *(const float4*)(rnn1 + ((size_t)b * T + tg) * 64 + 4 * k4);
            *(float4*)(Ks + tl * 68 + 4 * k4) = v;
        }
        __syncthreads();

        {
            float4 bse = *(const float4*)(base + l1_c0);
            float a00 = bse.x, a01 = bse.y, a02 = bse.z, a03 = bse.w;
            float a10 = bse.x, a11 = bse.y, a12 = bse.z, a13 = bse.w;
#pragma unroll 4
            for (int k4 = 0; k4 < 16; k4++) {
                float4 k0 = *(const float4*)(Ks + l1_t0 * 68 + 4 * k4);
                float4 k1 = *(const float4*)(Ks + (l1_t0 + 1) * 68 + 4 * k4);
                const float kk0[4] = {k0.x, k0.y, k0.z, k0.w};
                const float kk1[4] = {k1.x, k1.y, k1.z, k1.w};
#pragma unroll
                for (int kk = 0; kk < 4; kk++) {
                    float4 w = *(const float4*)(Weff + (4 * k4 + kk) * 80 + l1_c0);
                    a00 = fmaf(kk0[kk], w.x, a00); a01 = fmaf(kk0[kk], w.y, a01);
                    a02 = fmaf(kk0[kk], w.z, a02); a03 = fmaf(kk0[kk], w.w, a03);
                    a10 = fmaf(kk1[kk], w.x, a10); a11 = fmaf(kk1[kk], w.y, a11);
                    a12 = fmaf(kk1[kk], w.z, a12); a13 = fmaf(kk1[kk], w.w, a13);
                }
            }
            float4 o0 = make_float4(sigmoidf_fast(a00), sigmoidf_fast(a01),
                                    sigmoidf_fast(a02), sigmoidf_fast(a03));
            float4 o1 = make_float4(sigmoidf_fast(a10), sigmoidf_fast(a11),
                                    sigmoidf_fast(a12), sigmoidf_fast(a13));
            *(float4*)(d1s + l1_t0 * 80 + l1_c0) = o0;
            *(float4*)(d1s + (l1_t0 + 1) * 80 + l1_c0) = o1;
        }
        __syncthreads();

        if (tid < 160) {
            float4 bse = *(const float4*)(ba2s + l2_c0);
            float a00 = bse.x, a01 = bse.y, a02 = bse.z, a03 = bse.w;
            float a10 = bse.x, a11 = bse.y, a12 = bse.z, a13 = bse.w;
#pragma unroll 4
            for (int k4 = 0; k4 < 20; k4++) {
                float4 d0 = *(const float4*)(d1s + l2_t0 * 80 + 4 * k4);
                float4 d1 = *(const float4*)(d1s + (l2_t0 + 1) * 80 + 4 * k4);
                const float dd0[4] = {d0.x, d0.y, d0.z, d0.w};
                const float dd1[4] = {d1.x, d1.y, d1.z, d1.w};
#pragma unroll
                for (int kk = 0; kk < 4; kk++) {
                    float4 w = *(const float4*)(Wa2s + (4 * k4 + kk) * 40 + l2_c0);
                    a00 = fmaf(dd0[kk], w.x, a00); a01 = fmaf(dd0[kk], w.y, a01);
                    a02 = fmaf(dd0[kk], w.z, a02); a03 = fmaf(dd0[kk], w.w, a03);
                    a10 = fmaf(dd1[kk], w.x, a10); a11 = fmaf(dd1[kk], w.y, a11);
                    a12 = fmaf(dd1[kk], w.z, a12); a13 = fmaf(dd1[kk], w.w, a13);
                }
            }
            float4 o0 = make_float4(sigmoidf_fast(a00), sigmoidf_fast(a01),
                                    sigmoidf_fast(a02), sigmoidf_fast(a03));
            float4 o1 = make_float4(sigmoidf_fast(a10), sigmoidf_fast(a11),
                                    sigmoidf_fast(a12), sigmoidf_fast(a13));
            *(float4*)(d2s + l2_t0 * 40 + l2_c0) = o0;
            *(float4*)(d2s + (l2_t0 + 1) * 40 + l2_c0) = o1;
        }
        __syncthreads();

        if (tid < 32) {
            float acc = ba3v;
#pragma unroll
            for (int k4 = 0; k4 < 10; k4++) {
                float4 d = *(const float4*)(d2s + tid * 40 + 4 * k4);
                float4 w = *(const float4*)(Wa3s + 4 * k4);
                acc = fmaf(d.x, w.x, acc); acc = fmaf(d.y, w.y, acc);
                acc = fmaf(d.z, w.z, acc); acc = fmaf(d.w, w.w, acc);
            }
            int tg = tt0 + tid;
            if (tg < T) {
                float m = mask[(size_t)b * T + tg];
                sc[tg] = (m > 0.0f) ? acc : -1e9f;
            }
        }
        __syncthreads();
    }

    float v = (tid < T) ? sc[tid] : -FLT_MAX;
#pragma unroll
    for (int o = 16; o > 0; o >>= 1) v = fmaxf(v, __shfl_xor_sync(0xffffffffu, v, o));
    if ((tid & 31) == 0) red[tid >> 5] = v;
    __syncthreads();
    if (tid == 0) {
        float mx = red[0];
#pragma unroll
        for (int w = 1; w < 10; w++) mx = fmaxf(mx, red[w]);
        red[12] = mx;
    }
    __syncthreads();
    float mx = red[12];

    float e = (tid < T) ? __expf(sc[tid] - mx) : 0.0f;
    float s = e;
#pragma unroll
    for (int o = 16; o > 0; o >>= 1) s += __shfl_xor_sync(0xffffffffu, s, o);
    __syncthreads();
    if ((tid & 31) == 0) red[tid >> 5] = s;
    __syncthreads();
    if (tid == 0) {
        float sum = 0.0f;
#pragma unroll
        for (int w = 0; w < 10; w++) sum += red[w];
        red[13] = 1.0f / sum;
    }
    __syncthreads();
    if (tid < T) alpha[(size_t)b * T + tid] = e * red[13];
}

// ======================================================================
// FCN head + hist_sum (unchanged).
// ======================================================================
__global__ void fcn_kernel(const int* __restrict__ u, const int* __restrict__ ii,
                           const int* __restrict__ hist_i,
                           const float* __restrict__ item_emb,
                           const float* __restrict__ user_emb,
                           const float* __restrict__ final2,
                           const float* __restrict__ W1, const float* __restrict__ b1,
                           const float* __restrict__ p1,
                           const float* __restrict__ W2, const float* __restrict__ b2,
                           const float* __restrict__ p2,
                           const float* __restrict__ W3, const float* __restrict__ b3,
                           float* __restrict__ out)
{
    __shared__ float xs[320];
    __shared__ float h1s[128];
    __shared__ float h2s[40];

    const int b = blockIdx.x;
    const int tid = threadIdx.x;

    if (tid < 64) {
        const int* hi = hist_i + (size_t)b * T;
        float s0 = 0.f, s1 = 0.f, s2 = 0.f, s3 = 0.f;
        for (int t = 0; t < T; t += 4) {
            s0 += item_emb[(size_t)hi[t]     * 64 + tid];
            s1 += item_emb[(size_t)hi[t + 1] * 64 + tid];
            s2 += item_emb[(size_t)hi[t + 2] * 64 + tid];
            s3 += item_emb[(size_t)hi[t + 3] * 64 + tid];
        }
        xs[128 + tid] = (s0 + s1) + (s2 + s3);
    } else {
        int j = tid - 64;
        xs[j]       = user_emb[(size_t)u[b]  * 64 + j];
        xs[64 + j]  = item_emb[(size_t)ii[b] * 64 + j];
        xs[256 + j] = final2[(size_t)b * 64 + j];
    }
    __syncthreads();
    if (tid < 64) xs[192 + tid] = xs[64 + tid] * xs[128 + tid];
    __syncthreads();

    {
        float a0 = b1[tid], a1 = 0.0f;
#pragma unroll 8
        for (int k = 0; k < 320; k += 2) {
            a0 = fmaf(xs[k],     W1[k * 128 + tid],       a0);
            a1 = fmaf(xs[k + 1], W1[(k + 1) * 128 + tid], a1);
        }
        float h = a0 + a1;
        h1s[tid] = (h >= 0.0f) ? h : p1[tid] * h;
    }
    __syncthreads();

    if (tid < 40) {
        float a0 = b2[tid], a1 = 0.0f;
#pragma unroll 16
        for (int k = 0; k < 128; k += 2) {
            a0 = fmaf(h1s[k],     W2[k * 40 + tid],       a0);
            a1 = fmaf(h1s[k + 1], W2[(k + 1) * 40 + tid], a1);
        }
        float h = a0 + a1;
        h2s[tid] = (h >= 0.0f) ? h : p2[tid] * h;
    }
    __syncthreads();

    if (tid == 0) {
        float acc = b3[0];
#pragma unroll
        for (int k = 0; k < 40; k++) acc = fmaf(h2s[k], W3[k], acc);
        out[b] = acc;
    }
}

// ======================================================================
extern "C" void kernel_launch(void* const* d_in, const int* in_sizes, int n_in,
                              void* d_out, int out_size)
{
    const int*   u        = (const int*)d_in[0];
    const int*   ii       = (const int*)d_in[1];
    const int*   hist_i   = (const int*)d_in[2];
    const float* mask     = (const float*)d_in[3];
    const float* item_emb = (const float*)d_in[4];
    const float* user_emb = (const float*)d_in[5];
    const float* g1_Wg = (const float*)d_in[6];
    const float* g1_Ug = (const float*)d_in[7];
    const float* g1_bg = (const float*)d_in[8];
    const float* g1_Wc = (const float*)d_in[9];
    const float* g1_Uc = (const float*)d_in[10];
    const float* g1_bc = (const float*)d_in[11];
    const float* Wa1 = (const float*)d_in[12];
    const float* ba1 = (const float*)d_in[13];
    const float* Wa2 = (const float*)d_in[14];
    const float* ba2 = (const float*)d_in[15];
    const float* Wa3 = (const float*)d_in[16];
    const float* ba3 = (const float*)d_in[17];
    const float* g2_Wg = (const float*)d_in[18];
    const float* g2_Ug = (const float*)d_in[19];
    const float* g2_bg = (const float*)d_in[20];
    const float* g2_Wc = (const float*)d_in[21];
    const float* g2_Uc = (const float*)d_in[22];
    const float* g2_bc = (const float*)d_in[23];
    const float* W1 = (const float*)d_in[24];
    const float* b1 = (const float*)d_in[25];
    const float* p1 = (const float*)d_in[26];
    const float* W2 = (const float*)d_in[27];
    const float* b2 = (const float*)d_in[28];
    const float* p2 = (const float*)d_in[29];
    const float* W3 = (const float*)d_in[30];
    const float* b3 = (const float*)d_in[31];
    float* out = (float*)d_out;

    float *xg, *xc, *rnn1, *alpha, *final2;
    __nv_bfloat16 *bh1, *bl1, *bh2, *bl2;
    cudaGetSymbolAddress((void**)&xg,     g_xg);
    cudaGetSymbolAddress((void**)&xc,     g_xc);
    cudaGetSymbolAddress((void**)&rnn1,   g_rnn1);
    cudaGetSymbolAddress((void**)&alpha,  g_alpha);
    cudaGetSymbolAddress((void**)&final2, g_final2);
    cudaGetSymbolAddress((void**)&bh1, g_bh1);
    cudaGetSymbolAddress((void**)&bl1, g_bl1);
    cudaGetSymbolAddress((void**)&bh2, g_bh2);
    cudaGetSymbolAddress((void**)&bl2, g_bl2);

    const int GRU_SMEM  = (128 * 68 + 64 * 68 + 3 * GR * 64) * 4;
    const int ATTN_SMEM = (64*80 + 80 + 80*40 + 40 + 40 + 64
                         + 32*68 + 32*80 + 32*40 + 224 + 16) * 4;

    cudaFuncSetAttribute(proj_mma_kernel<0>, cudaFuncAttributeMaxDynamicSharedMemorySize, PSM_TOTAL);
    cudaFuncSetAttribute(proj_mma_kernel<1>, cudaFuncAttributeMaxDynamicSharedMemorySize, PSM_TOTAL);
    cudaFuncSetAttribute(gru_kernel<true>,  cudaFuncAttributeMaxDynamicSharedMemorySize, GRU_SMEM);
    cudaFuncSetAttribute(gru_kernel<false>, cudaFuncAttributeMaxDynamicSharedMemorySize, GRU_SMEM);
    cudaFuncSetAttribute(attn_kernel, cudaFuncAttributeMaxDynamicSharedMemorySize, ATTN_SMEM);

    const int GRU_GRID = (B + GR - 1) / GR;

    // 0) split projection weights to bf16 hi/lo (both GRUs)
    wsplit_kernel<<<48, 256>>>(g1_Wg, g1_Wc, bh1, bl1);
    wsplit_kernel<<<48, 256>>>(g2_Wg, g2_Wc, bh2, bl2);
    // 1) GRU1 input projections via HMMA tensor cores
    proj_mma_kernel<0><<<BT / 128, 256, PSM_TOTAL>>>(item_emb, hist_i, nullptr,
                                                     bh1, bl1, g1_bg, g1_bc, xg, xc);
    // 2) GRU1 recurrence -> rnn1
    gru_kernel<true><<<GRU_GRID, 128, GRU_SMEM>>>(xg, xc, mask, g1_Ug, g1_Uc, rnn1);
    // 3) DIN attention -> alpha
    attn_kernel<<<B, 320, ATTN_SMEM>>>(ii, item_emb, rnn1, mask,
                                       Wa1, ba1, Wa2, ba2, Wa3, ba3, alpha);
    // 4) GRU2 input projections via HMMA (rnn1 * alpha)
    proj_mma_kernel<1><<<BT / 128, 256, PSM_TOTAL>>>(rnn1, nullptr, alpha,
                                                     bh2, bl2, g2_bg, g2_bc, xg, xc);
    // 5) GRU2 recurrence -> final2 only
    gru_kernel<false><<<GRU_GRID, 128, GRU_SMEM>>>(xg, xc, mask, g2_Ug, g2_Uc, final2);
    // 6) FCN head -> logits
    fcn_kernel<<<B, 128>>>(u, ii, hist_i, item_emb, user_emb, final2,
                           W1, b1, p1, W2, b2, p2, W3, b3, out);
}

// round 7
// speedup vs baseline: 1.9025x; 1.0273x over previous
#include <cuda_runtime.h>
#include <cuda_bf16.h>
#include <math.h>
#include <float.h>
#include <cstdint>

#define B 4096
#define T 200
#define BT (B*T)
#define GR 10   // batch rows per GRU block

// ---------------- scratch (device globals: no allocs allowed) ----------------
__device__ float g_xg[(size_t)BT * 128];
__device__ float g_xc[(size_t)BT * 64];
__device__ float g_rnn1[(size_t)BT * 64];
__device__ float g_alpha[BT];
__device__ float g_final2[B * 64];
// split-bf16 weights for the two projection GEMMs: layout [n(192)][k(64)]
__device__ __nv_bfloat16 g_bh1[192 * 64];
__device__ __nv_bfloat16 g_bl1[192 * 64];
__device__ __nv_bfloat16 g_bh2[192 * 64];
__device__ __nv_bfloat16 g_bl2[192 * 64];

__device__ __forceinline__ float sigmoidf_fast(float x) {
    return 1.0f / (1.0f + __expf(-x));
}

__device__ __forceinline__ uint32_t smem_u32(const void* p) {
    uint32_t a;
    asm("{ .reg .u64 t; cvta.to.shared.u64 t, %1; cvt.u32.u64 %0, t; }" : "=r"(a) : "l"(p));
    return a;
}
__device__ __forceinline__ void ldsm_x4(uint32_t& r0, uint32_t& r1, uint32_t& r2, uint32_t& r3,
                                        uint32_t addr) {
    asm volatile("ldmatrix.sync.aligned.m8n8.x4.shared.b16 {%0,%1,%2,%3}, [%4];"
                 : "=r"(r0), "=r"(r1), "=r"(r2), "=r"(r3) : "r"(addr));
}
__device__ __forceinline__ void mma16816(float* c, const uint32_t* a, uint32_t b0, uint32_t b1) {
    asm volatile("mma.sync.aligned.m16n8k16.row.col.f32.bf16.bf16.f32 "
                 "{%0,%1,%2,%3}, {%4,%5,%6,%7}, {%8,%9}, {%0,%1,%2,%3};"
                 : "+f"(c[0]), "+f"(c[1]), "+f"(c[2]), "+f"(c[3])
                 : "r"(a[0]), "r"(a[1]), "r"(a[2]), "r"(a[3]), "r"(b0), "r"(b1));
}

// ======================================================================
// Weight split prep: W[64,128]|[64,64] fp32 -> Bhi/Blo [n=192][k=64] bf16
// ======================================================================
__global__ void wsplit_kernel(const float* __restrict__ Wg, const float* __restrict__ Wc,
                              __nv_bfloat16* __restrict__ Bhi, __nv_bfloat16* __restrict__ Blo)
{
    int idx = blockIdx.x * 256 + threadIdx.x;
    if (idx >= 192 * 64) return;
    int n = idx >> 6, k = idx & 63;
    float w = (n < 128) ? Wg[k * 128 + n] : Wc[k * 64 + (n - 128)];
    __nv_bfloat16 hi = __float2bfloat16(w);
    __nv_bfloat16 lo = __float2bfloat16(w - __bfloat162float(hi));
    Bhi[idx] = hi;
    Blo[idx] = lo;
}

// ======================================================================
// HMMA projection: D[128 x 192] = A[128x64] @ W + bias (unchanged, passing).
// ======================================================================
#define PAD_K 72   // bf16 elements per smem row (144 B)
#define PSM_BIAS 0
#define PSM_AHI  768
#define PSM_ALO  (PSM_AHI + 128 * PAD_K * 2)
#define PSM_BHI  (PSM_ALO + 128 * PAD_K * 2)
#define PSM_BLO  (PSM_BHI + 192 * PAD_K * 2)
#define PSM_TOTAL (PSM_BLO + 192 * PAD_K * 2)   // 92928 bytes

template<int MODE>
__global__ void __launch_bounds__(256, 2) proj_mma_kernel(
        const float* __restrict__ src,
        const int*   __restrict__ hist_i,
        const float* __restrict__ alpha,
        const __nv_bfloat16* __restrict__ Bhi,
        const __nv_bfloat16* __restrict__ Blo,
        const float* __restrict__ bg,
        const float* __restrict__ bc,
        float* __restrict__ xg,
        float* __restrict__ xc)
{
    extern __shared__ char smem[];
    const uint32_t sbase = smem_u32(smem);
    const int tid = threadIdx.x;
    const int wid = tid >> 5;
    const int lane = tid & 31;
    const int m0 = blockIdx.x * 128;

    float* bs = (float*)(smem + PSM_BIAS);
    if (tid < 192) bs[tid] = (tid < 128) ? bg[tid] : bc[tid - 128];

    {
        const uint4* sh = (const uint4*)Bhi;
        const uint4* sl = (const uint4*)Blo;
#pragma unroll
        for (int i = 0; i < 6; i++) {
            int idx = tid + 256 * i;               // < 1536
            int n = idx >> 3, seg = idx & 7;
            int off = n * (PAD_K * 2) + seg * 16;
            *(uint4*)(smem + PSM_BHI + off) = sh[idx];
            *(uint4*)(smem + PSM_BLO + off) = sl[idx];
        }
    }

    {
        const int r = tid >> 1;
        const int half = tid & 1;
        const float* srow;
        float scale = 1.0f;
        if (MODE == 0) {
            srow = src + (size_t)hist_i[m0 + r] * 64;
        } else {
            srow = src + (size_t)(m0 + r) * 64;
            scale = alpha[m0 + r];
        }
        srow += half * 32;
        const int kb = half * 32;
#pragma unroll
        for (int c = 0; c < 4; c++) {
            float4 v0 = *(const float4*)(srow + 8 * c);
            float4 v1 = *(const float4*)(srow + 8 * c + 4);
            float vv[8] = {v0.x, v0.y, v0.z, v0.w, v1.x, v1.y, v1.z, v1.w};
            __nv_bfloat16 hb[8], lb[8];
#pragma unroll
            for (int e = 0; e < 8; e++) {
                float f = vv[e] * scale;
                hb[e] = __float2bfloat16(f);
                lb[e] = __float2bfloat16(f - __bfloat162float(hb[e]));
            }
            int off = r * (PAD_K * 2) + (kb + 8 * c) * 2;
            *(uint4*)(smem + PSM_AHI + off) = *(uint4*)hb;
            *(uint4*)(smem + PSM_ALO + off) = *(uint4*)lb;
        }
    }
    __syncthreads();

    const int arow = wid * 16 + (lane & 15);
    const int acolb = ((lane >> 4) << 3);
    const uint32_t a_off = (uint32_t)arow * (PAD_K * 2) + acolb * 2;
    const uint32_t aH_base = sbase + PSM_AHI + a_off;
    const uint32_t aL_base = sbase + PSM_ALO + a_off;

    const int bnrow_l = (lane & 7) + ((lane & 16) >> 1);
    const int bcol_l = (lane & 8);
    const uint32_t b_off_l = (uint32_t)bnrow_l * (PAD_K * 2) + bcol_l * 2;

    const int g = lane >> 2;
    const int tq = lane & 3;

#pragma unroll
    for (int nh = 0; nh < 2; nh++) {
        const uint32_t bH_base = sbase + PSM_BHI + b_off_l + (uint32_t)nh * 96 * (PAD_K * 2);
        const uint32_t bL_base = sbase + PSM_BLO + b_off_l + (uint32_t)nh * 96 * (PAD_K * 2);

        float acc[12][4];
#pragma unroll
        for (int i = 0; i < 12; i++)
#pragma unroll
            for (int q = 0; q < 4; q++) acc[i][q] = 0.0f;

#pragma unroll
        for (int ks = 0; ks < 4; ks++) {
            uint32_t aH[4], aL[4];
            ldsm_x4(aH[0], aH[1], aH[2], aH[3], aH_base + ks * 32);
            ldsm_x4(aL[0], aL[1], aL[2], aL[3], aL_base + ks * 32);
#pragma unroll
            for (int np = 0; np < 6; np++) {
                uint32_t bh0, bh1, bh2, bh3;
                ldsm_x4(bh0, bh1, bh2, bh3,
                        bH_base + (uint32_t)np * 16 * (PAD_K * 2) + ks * 32);
                mma16816(acc[2 * np],     aH, bh0, bh1);
                mma16816(acc[2 * np + 1], aH, bh2, bh3);
                mma16816(acc[2 * np],     aL, bh0, bh1);
                mma16816(acc[2 * np + 1], aL, bh2, bh3);
                uint32_t bl0, bl1, bl2, bl3;
                ldsm_x4(bl0, bl1, bl2, bl3,
                        bL_base + (uint32_t)np * 16 * (PAD_K * 2) + ks * 32);
                mma16816(acc[2 * np],     aH, bl0, bl1);
                mma16816(acc[2 * np + 1], aH, bl2, bl3);
            }
        }

        const int r0 = m0 + wid * 16 + g;
        const int r1 = r0 + 8;
#pragma unroll
        for (int nt = 0; nt < 12; nt++) {
            const int n = nh * 96 + nt * 8 + 2 * tq;
            const float bx = bs[n], by = bs[n + 1];
            float2 o0 = make_float2(acc[nt][0] + bx, acc[nt][1] + by);
            float2 o1 = make_float2(acc[nt][2] + bx, acc[nt][3] + by);
            if (n < 128) {
                *(float2*)(xg + (size_t)r0 * 128 + n) = o0;
                *(float2*)(xg + (size_t)r1 * 128 + n) = o1;
            } else {
                *(float2*)(xc + (size_t)r0 * 64 + (n - 128)) = o0;
                *(float2*)(xc + (size_t)r1 * 64 + (n - 128)) = o1;
            }
        }
    }
}

// ======================================================================
// GRU recurrence v3: 128 threads x GR rows.
//  - gate phase: all 128 threads, one gate column each (unchanged)
//  - candidate phase: ALL 128 threads; thread pair (2c,2c+1) splits k
//    in halves, combined with shfl_xor(1). Uc/rhs use 72-stride +36-offset
//    split layout (conflict-free LDS.128).
//  - mask preloaded to smem once (removes dependent LDG from the t-loop).
// ======================================================================
template<bool STORE_ALL>
__global__ void __launch_bounds__(128) gru_kernel(
                           const float* __restrict__ xg,
                           const float* __restrict__ xc,
                           const float* __restrict__ mask,
                           const float* __restrict__ Ug,  // [64,128]
                           const float* __restrict__ Uc,  // [64,64]
                           float* __restrict__ out)
{
    extern __shared__ float sm[];
    float* UgsT = sm;                     // [128][68]
    float* UcsT = UgsT + 128 * 68;        // [64][72] split layout
    float* hs   = UcsT + 64 * 72;         // [GR][64]
    float* rhs  = hs + GR * 64;           // [GR][72] split layout
    float* zs   = rhs + GR * 72;          // [GR][64]
    float* msk  = zs + GR * 64;           // [GR][T]

    const int j = threadIdx.x;            // 0..127
    const int b0 = blockIdx.x * GR;
    const int c = j >> 1;                 // candidate column 0..63
    const int half = j & 1;

    for (int idx = j; idx < 128 * 64; idx += 128) {
        int k = idx >> 7, jj = idx & 127;
        UgsT[jj * 68 + k] = Ug[idx];
    }
    for (int idx = j; idx < 64 * 64; idx += 128) {
        int k = idx >> 6, cc = idx & 63;
        UcsT[cc * 72 + (k >> 5) * 36 + (k & 31)] = Uc[idx];
    }
    for (int idx = j; idx < GR * 64; idx += 128) hs[idx] = 0.0f;

    int br[GR];
    bool val[GR];
#pragma unroll
    for (int r = 0; r < GR; r++) {
        int b = b0 + r;
        val[r] = (b < B);
        br[r] = val[r] ? b : (B - 1);
    }

    // mask -> smem
    for (int idx = j; idx < GR * T; idx += 128) {
        int r = idx / T, t = idx - r * T;
        msk[idx] = mask[(size_t)br[r] * T + t];
    }
    __syncthreads();

    float xgv[GR];
#pragma unroll
    for (int r = 0; r < GR; r++)
        xgv[r] = xg[(size_t)br[r] * T * 128 + j];

    const float* wc_base = UcsT + c * 72 + half * 36;

    for (int t = 0; t < T; t++) {
        // ---- gate phase (all 128 threads, column j) ----
        float acc[GR];
#pragma unroll
        for (int r = 0; r < GR; r++) acc[r] = xgv[r];

#pragma unroll 4
        for (int k4 = 0; k4 < 16; k4++) {
            float4 w = *(const float4*)(UgsT + j * 68 + 4 * k4);
#pragma unroll
            for (int r = 0; r < GR; r++) {
                float4 h4 = *(const float4*)(hs + r * 64 + 4 * k4);
                acc[r] = fmaf(h4.x, w.x, acc[r]);
                acc[r] = fmaf(h4.y, w.y, acc[r]);
                acc[r] = fmaf(h4.z, w.z, acc[r]);
                acc[r] = fmaf(h4.w, w.w, acc[r]);
            }
        }

        // prefetch next xg
        if (t + 1 < T) {
#pragma unroll
            for (int r = 0; r < GR; r++)
                xgv[r] = xg[(size_t)br[r] * T * 128 + (t + 1) * 128 + j];
        }

#pragma unroll
        for (int r = 0; r < GR; r++) {
            float g = sigmoidf_fast(acc[r]);
            if (j < 64) rhs[r * 72 + (j >> 5) * 36 + (j & 31)] = g * hs[r * 64 + j];
            else        zs[r * 64 + (j - 64)] = g;
        }
        __syncthreads();

        // ---- candidate phase (ALL 128 threads; pair-split k) ----
        {
            float cacc[GR];
#pragma unroll
            for (int r = 0; r < GR; r++)
                cacc[r] = (half == 0) ? xc[(size_t)br[r] * T * 64 + t * 64 + c] : 0.0f;

#pragma unroll 4
            for (int k4 = 0; k4 < 8; k4++) {
                float4 w = *(const float4*)(wc_base + 4 * k4);
#pragma unroll
                for (int r = 0; r < GR; r++) {
                    float4 rh = *(const float4*)(rhs + r * 72 + half * 36 + 4 * k4);
                    cacc[r] = fmaf(rh.x, w.x, cacc[r]);
                    cacc[r] = fmaf(rh.y, w.y, cacc[r]);
                    cacc[r] = fmaf(rh.z, w.z, cacc[r]);
                    cacc[r] = fmaf(rh.w, w.w, cacc[r]);
                }
            }

#pragma unroll
            for (int r = 0; r < GR; r++) {
                float tot = cacc[r] + __shfl_xor_sync(0xffffffffu, cacc[r], 1);
                float cc = tanhf(tot);
                float z = zs[r * 64 + c];
                float h = hs[r * 64 + c];
                float hn = fmaf(z, h - cc, cc);         // z*h + (1-z)*c
                float m = msk[r * T + t];
                float hnew = fmaf(m, hn - h, h);
                if (half == 0) {
                    hs[r * 64 + c] = hnew;
                    if (STORE_ALL && val[r])
                        out[(size_t)br[r] * T * 64 + t * 64 + c] = hnew;
                }
            }
        }
        __syncthreads();
    }

    if (!STORE_ALL && j < 64) {
#pragma unroll
        for (int r = 0; r < GR; r++)
            if (val[r]) out[(size_t)br[r] * 64 + j] = hs[r * 64 + j];
    }
}

// ======================================================================
// DIN attention (unchanged).
// ======================================================================
__global__ void __launch_bounds__(320) attn_kernel(
                            const int*   __restrict__ item_i,
                            const float* __restrict__ item_emb,
                            const float* __restrict__ rnn1,
                            const float* __restrict__ mask,
                            const float* __restrict__ Wa1, const float* __restrict__ ba1,
                            const float* __restrict__ Wa2, const float* __restrict__ ba2,
                            const float* __restrict__ Wa3, const float* __restrict__ ba3,
                            float* __restrict__ alpha)
{
    extern __shared__ float sm[];
    float* Weff = sm;
    float* base = Weff + 64 * 80;
    float* Wa2s = base + 80;
    float* ba2s = Wa2s + 80 * 40;
    float* Wa3s = ba2s + 40;
    float* qs   = Wa3s + 40;
    float* Ks   = qs + 64;
    float* d1s  = Ks + 32 * 68;
    float* d2s  = d1s + 32 * 80;
    float* sc   = d2s + 32 * 40;
    float* red  = sc + 224;

    const int b = blockIdx.x;
    const int tid = threadIdx.x;

    const int l1_t0 = (tid / 20) * 2;
    const int l1_c0 = (tid % 20) * 4;
    const int l2_t0 = (tid / 10) * 2;
    const int l2_c0 = (tid % 10) * 4;

    if (tid < 64) qs[tid] = item_emb[(size_t)item_i[b] * 64 + tid];
    __syncthreads();

    if (tid < 80) {
        int c = tid;
        float acc = ba1[c];
#pragma unroll 8
        for (int k = 0; k < 64; k++)
            acc = fmaf(qs[k], Wa1[k * 80 + c] + Wa1[(128 + k) * 80 + c], acc);
        base[c] = acc;
    }
    for (int idx = tid; idx < 64 * 80; idx += 320) {
        int k = idx / 80, c = idx - k * 80;
        Weff[idx] = Wa1[(64 + k) * 80 + c] - Wa1[(128 + k) * 80 + c]
                  + qs[k] * Wa1[(192 + k) * 80 + c];
    }
    for (int idx = tid; idx < 80 * 40; idx += 320) Wa2s[idx] = Wa2[idx];
    if (tid < 40) { ba2s[tid] = ba2[tid]; Wa3s[tid] = Wa3[tid]; }
    __syncthreads();

    const float ba3v = ba3[0];

    for (int cc = 0; cc < 7; cc++) {
        const int tt0 = cc * 32;

        for (int idx = tid; idx < 512; idx += 320) {
            int tl = idx >> 4, k4 = idx & 15;
            int tg = tt0 + tl; if (tg > T - 1) tg = T - 1;
            float4 v = *(const float4*)(rnn1 + ((size_t)b * T + tg) * 64 + 4 * k4);
            *(float4*)(Ks + tl * 68 + 4 * k4) = v;
        }
        __syncthreads();

        {
            float4 bse = *(const float4*)(base + l1_c0);
            float a00 = bse.x, a01 = bse.y, a02 = bse.z, a03 = bse.w;
            float a10 = bse.x, a11 = bse.y, a12 = bse.z, a13 = bse.w;
#pragma unroll 4
            for (int k4 = 0; k4 < 16; k4++) {
                float4 k0 = *(const float4*)(Ks + l1_t0 * 68 + 4 * k4);
                float4 k1 = *(const float4*)(Ks + (l1_t0 + 1) * 68 + 4 * k4);
                const float kk0[4] = {k0.x, k0.y, k0.z, k0.w};
                const float kk1[4] = {k1.x, k1.y, k1.z, k1.w};
#pragma unroll
                for (int kk = 0; kk < 4; kk++) {
                    float4 w = *(const float4*)(Weff + (4 * k4 + kk) * 80 + l1_c0);
                    a00 = fmaf(kk0[kk], w.x, a00); a01 = fmaf(kk0[kk], w.y, a01);
                    a02 = fmaf(kk0[kk], w.z, a02); a03 = fmaf(kk0[kk], w.w, a03);
                    a10 = fmaf(kk1[kk], w.x, a10); a11 = fmaf(kk1[kk], w.y, a11);
                    a12 = fmaf(kk1[kk], w.z, a12); a13 = fmaf(kk1[kk], w.w, a13);
                }
            }
            float4 o0 = make_float4(sigmoidf_fast(a00), sigmoidf_fast(a01),
                                    sigmoidf_fast(a02), sigmoidf_fast(a03));
            float4 o1 = make_float4(sigmoidf_fast(a10), sigmoidf_fast(a11),
                                    sigmoidf_fast(a12), sigmoidf_fast(a13));
            *(float4*)(d1s + l1_t0 * 80 + l1_c0) = o0;
            *(float4*)(d1s + (l1_t0 + 1) * 80 + l1_c0) = o1;
        }
        __syncthreads();

        if (tid < 160) {
            float4 bse = *(const float4*)(ba2s + l2_c0);
            float a00 = bse.x, a01 = bse.y, a02 = bse.z, a03 = bse.w;
            float a10 = bse.x, a11 = bse.y, a12 = bse.z, a13 = bse.w;
#pragma unroll 4
            for (int k4 = 0; k4 < 20; k4++) {
                float4 d0 = *(const float4*)(d1s + l2_t0 * 80 + 4 * k4);
                float4 d1 = *(const float4*)(d1s + (l2_t0 + 1) * 80 + 4 * k4);
                const float dd0[4] = {d0.x, d0.y, d0.z, d0.w};
                const float dd1[4] = {d1.x, d1.y, d1.z, d1.w};
#pragma unroll
                for (int kk = 0; kk < 4; kk++) {
                    float4 w = *(const float4*)(Wa2s + (4 * k4 + kk) * 40 + l2_c0);
                    a00 = fmaf(dd0[kk], w.x, a00); a01 = fmaf(dd0[kk], w.y, a01);
                    a02 = fmaf(dd0[kk], w.z, a02); a03 = fmaf(dd0[kk], w.w, a03);
                    a10 = fmaf(dd1[kk], w.x, a10); a11 = fmaf(dd1[kk], w.y, a11);
                    a12 = fmaf(dd1[kk], w.z, a12); a13 = fmaf(dd1[kk], w.w, a13);
                }
            }
            float4 o0 = make_float4(sigmoidf_fast(a00), sigmoidf_fast(a01),
                                    sigmoidf_fast(a02), sigmoidf_fast(a03));
            float4 o1 = make_float4(sigmoidf_fast(a10), sigmoidf_fast(a11),
                                    sigmoidf_fast(a12), sigmoidf_fast(a13));
            *(float4*)(d2s + l2_t0 * 40 + l2_c0) = o0;
            *(float4*)(d2s + (l2_t0 + 1) * 40 + l2_c0) = o1;
        }
        __syncthreads();

        if (tid < 32) {
            float acc = ba3v;
#pragma unroll
            for (int k4 = 0; k4 < 10; k4++) {
                float4 d = *(const float4*)(d2s + tid * 40 + 4 * k4);
                float4 w = *(const float4*)(Wa3s + 4 * k4);
                acc = fmaf(d.x, w.x, acc); acc = fmaf(d.y, w.y, acc);
                acc = fmaf(d.z, w.z, acc); acc = fmaf(d.w, w.w, acc);
            }
            int tg = tt0 + tid;
            if (tg < T) {
                float m = mask[(size_t)b * T + tg];
                sc[tg] = (m > 0.0f) ? acc : -1e9f;
            }
        }
        __syncthreads();
    }

    float v = (tid < T) ? sc[tid] : -FLT_MAX;
#pragma unroll
    for (int o = 16; o > 0; o >>= 1) v = fmaxf(v, __shfl_xor_sync(0xffffffffu, v, o));
    if ((tid & 31) == 0) red[tid >> 5] = v;
    __syncthreads();
    if (tid == 0) {
        float mx = red[0];
#pragma unroll
        for (int w = 1; w < 10; w++) mx = fmaxf(mx, red[w]);
        red[12] = mx;
    }
    __syncthreads();
    float mx = red[12];

    float e = (tid < T) ? __expf(sc[tid] - mx) : 0.0f;
    float s = e;
#pragma unroll
    for (int o = 16; o > 0; o >>= 1) s += __shfl_xor_sync(0xffffffffu, s, o);
    __syncthreads();
    if ((tid & 31) == 0) red[tid >> 5] = s;
    __syncthreads();
    if (tid == 0) {
        float sum = 0.0f;
#pragma unroll
        for (int w = 0; w < 10; w++) sum += red[w];
        red[13] = 1.0f / sum;
    }
    __syncthreads();
    if (tid < T) alpha[(size_t)b * T + tid] = e * red[13];
}

// ======================================================================
// FCN head + hist_sum (unchanged).
// ======================================================================
__global__ void fcn_kernel(const int* __restrict__ u, const int* __restrict__ ii,
                           const int* __restrict__ hist_i,
                           const float* __restrict__ item_emb,
                           const float* __restrict__ user_emb,
                           const float* __restrict__ final2,
                           const float* __restrict__ W1, const float* __restrict__ b1,
                           const float* __restrict__ p1,
                           const float* __restrict__ W2, const float* __restrict__ b2,
                           const float* __restrict__ p2,
                           const float* __restrict__ W3, const float* __restrict__ b3,
                           float* __restrict__ out)
{
    __shared__ float xs[320];
    __shared__ float h1s[128];
    __shared__ float h2s[40];

    const int b = blockIdx.x;
    const int tid = threadIdx.x;

    if (tid < 64) {
        const int* hi = hist_i + (size_t)b * T;
        float s0 = 0.f, s1 = 0.f, s2 = 0.f, s3 = 0.f;
        for (int t = 0; t < T; t += 4) {
            s0 += item_emb[(size_t)hi[t]     * 64 + tid];
            s1 += item_emb[(size_t)hi[t + 1] * 64 + tid];
            s2 += item_emb[(size_t)hi[t + 2] * 64 + tid];
            s3 += item_emb[(size_t)hi[t + 3] * 64 + tid];
        }
        xs[128 + tid] = (s0 + s1) + (s2 + s3);
    } else {
        int j = tid - 64;
        xs[j]       = user_emb[(size_t)u[b]  * 64 + j];
        xs[64 + j]  = item_emb[(size_t)ii[b] * 64 + j];
        xs[256 + j] = final2[(size_t)b * 64 + j];
    }
    __syncthreads();
    if (tid < 64) xs[192 + tid] = xs[64 + tid] * xs[128 + tid];
    __syncthreads();

    {
        float a0 = b1[tid], a1 = 0.0f;
#pragma unroll 8
        for (int k = 0; k < 320; k += 2) {
            a0 = fmaf(xs[k],     W1[k * 128 + tid],       a0);
            a1 = fmaf(xs[k + 1], W1[(k + 1) * 128 + tid], a1);
        }
        float h = a0 + a1;
        h1s[tid] = (h >= 0.0f) ? h : p1[tid] * h;
    }
    __syncthreads();

    if (tid < 40) {
        float a0 = b2[tid], a1 = 0.0f;
#pragma unroll 16
        for (int k = 0; k < 128; k += 2) {
            a0 = fmaf(h1s[k],     W2[k * 40 + tid],       a0);
            a1 = fmaf(h1s[k + 1], W2[(k + 1) * 40 + tid], a1);
        }
        float h = a0 + a1;
        h2s[tid] = (h >= 0.0f) ? h : p2[tid] * h;
    }
    __syncthreads();

    if (tid == 0) {
        float acc = b3[0];
#pragma unroll
        for (int k = 0; k < 40; k++) acc = fmaf(h2s[k], W3[k], acc);
        out[b] = acc;
    }
}

// ======================================================================
extern "C" void kernel_launch(void* const* d_in, const int* in_sizes, int n_in,
                              void* d_out, int out_size)
{
    const int*   u        = (const int*)d_in[0];
    const int*   ii       = (const int*)d_in[1];
    const int*   hist_i   = (const int*)d_in[2];
    const float* mask     = (const float*)d_in[3];
    const float* item_emb = (const float*)d_in[4];
    const float* user_emb = (const float*)d_in[5];
    const float* g1_Wg = (const float*)d_in[6];
    const float* g1_Ug = (const float*)d_in[7];
    const float* g1_bg = (const float*)d_in[8];
    const float* g1_Wc = (const float*)d_in[9];
    const float* g1_Uc = (const float*)d_in[10];
    const float* g1_bc = (const float*)d_in[11];
    const float* Wa1 = (const float*)d_in[12];
    const float* ba1 = (const float*)d_in[13];
    const float* Wa2 = (const float*)d_in[14];
    const float* ba2 = (const float*)d_in[15];
    const float* Wa3 = (const float*)d_in[16];
    const float* ba3 = (const float*)d_in[17];
    const float* g2_Wg = (const float*)d_in[18];
    const float* g2_Ug = (const float*)d_in[19];
    const float* g2_bg = (const float*)d_in[20];
    const float* g2_Wc = (const float*)d_in[21];
    const float* g2_Uc = (const float*)d_in[22];
    const float* g2_bc = (const float*)d_in[23];
    const float* W1 = (const float*)d_in[24];
    const float* b1 = (const float*)d_in[25];
    const float* p1 = (const float*)d_in[26];
    const float* W2 = (const float*)d_in[27];
    const float* b2 = (const float*)d_in[28];
    const float* p2 = (const float*)d_in[29];
    const float* W3 = (const float*)d_in[30];
    const float* b3 = (const float*)d_in[31];
    float* out = (float*)d_out;

    float *xg, *xc, *rnn1, *alpha, *final2;
    __nv_bfloat16 *bh1, *bl1, *bh2, *bl2;
    cudaGetSymbolAddress((void**)&xg,     g_xg);
    cudaGetSymbolAddress((void**)&xc,     g_xc);
    cudaGetSymbolAddress((void**)&rnn1,   g_rnn1);
    cudaGetSymbolAddress((void**)&alpha,  g_alpha);
    cudaGetSymbolAddress((void**)&final2, g_final2);
    cudaGetSymbolAddress((void**)&bh1, g_bh1);
    cudaGetSymbolAddress((void**)&bl1, g_bl1);
    cudaGetSymbolAddress((void**)&bh2, g_bh2);
    cudaGetSymbolAddress((void**)&bl2, g_bl2);

    const int GRU_SMEM  = (128 * 68 + 64 * 72 + GR * 64 + GR * 72 + GR * 64 + GR * T) * 4;
    const int ATTN_SMEM = (64*80 + 80 + 80*40 + 40 + 40 + 64
                         + 32*68 + 32*80 + 32*40 + 224 + 16) * 4;

    cudaFuncSetAttribute(proj_mma_kernel<0>, cudaFuncAttributeMaxDynamicSharedMemorySize, PSM_TOTAL);
    cudaFuncSetAttribute(proj_mma_kernel<1>, cudaFuncAttributeMaxDynamicSharedMemorySize, PSM_TOTAL);
    cudaFuncSetAttribute(gru_kernel<true>,  cudaFuncAttributeMaxDynamicSharedMemorySize, GRU_SMEM);
    cudaFuncSetAttribute(gru_kernel<false>, cudaFuncAttributeMaxDynamicSharedMemorySize, GRU_SMEM);
    cudaFuncSetAttribute(attn_kernel, cudaFuncAttributeMaxDynamicSharedMemorySize, ATTN_SMEM);

    const int GRU_GRID = (B + GR - 1) / GR;

    // 0) split projection weights to bf16 hi/lo (both GRUs)
    wsplit_kernel<<<48, 256>>>(g1_Wg, g1_Wc, bh1, bl1);
    wsplit_kernel<<<48, 256>>>(g2_Wg, g2_Wc, bh2, bl2);
    // 1) GRU1 input projections via HMMA tensor cores
    proj_mma_kernel<0><<<BT / 128, 256, PSM_TOTAL>>>(item_emb, hist_i, nullptr,
                                                     bh1, bl1, g1_bg, g1_bc, xg, xc);
    // 2) GRU1 recurrence -> rnn1
    gru_kernel<true><<<GRU_GRID, 128, GRU_SMEM>>>(xg, xc, mask, g1_Ug, g1_Uc, rnn1);
    // 3) DIN attention -> alpha
    attn_kernel<<<B, 320, ATTN_SMEM>>>(ii, item_emb, rnn1, mask,
                                       Wa1, ba1, Wa2, ba2, Wa3, ba3, alpha);
    // 4) GRU2 input projections via HMMA (rnn1 * alpha)
    proj_mma_kernel<1><<<BT / 128, 256, PSM_TOTAL>>>(rnn1, nullptr, alpha,
                                                     bh2, bl2, g2_bg, g2_bc, xg, xc);
    // 5) GRU2 recurrence -> final2 only
    gru_kernel<false><<<GRU_GRID, 128, GRU_SMEM>>>(xg, xc, mask, g2_Ug, g2_Uc, final2);
    // 6) FCN head -> logits
    fcn_kernel<<<B, 128>>>(u, ii, hist_i, item_emb, user_emb, final2,
                           W1, b1, p1, W2, b2, p2, W3, b3, out);
}